// round 1
// baseline (speedup 1.0000x reference)
#include <cuda_runtime.h>
#include <math.h>

#define NN    40000
#define INITD 100
#define DD    200
#define FF    4
#define EE    800000
#define NRELD 800
#define BB    2048
#define HH2   100
#define NPAIR 6
#define FD    (FF*DD)   // 800

// output layout: sub_emb (B,FD), rel_emb (B,FD), x (N,FD), mi_loss (1)
#define SUB_OFF 0
#define REL_OFF ((size_t)BB*FD)
#define X_OFF   ((size_t)2*BB*FD)
#define MI_OFF  ((size_t)2*BB*FD + (size_t)NN*FD)

// ---------------- scratch (device globals; no allocation allowed) ----------
__device__ float g_xA[(size_t)NN*FD];
__device__ float g_xB[(size_t)NN*FD];
__device__ float g_kw[(size_t)NN*FD];
__device__ float g_r1[NRELD*DD];
__device__ float g_h[12*BB*HH2];
__device__ int   g_deg[NN];
__device__ int   g_cur[NN];
__device__ int   g_rowptr[NN+1];
__device__ int   g_csrc[EE];
__device__ int   g_cet[EE];
__device__ int   g_bsums[256];
__device__ int   g_boffs[256];

// ---------------- CSR build -------------------------------------------------
__global__ void k_zero(float* mi) {
    int i = blockIdx.x*blockDim.x + threadIdx.x;
    if (i < NN) { g_deg[i] = 0; g_cur[i] = 0; }
    if (i == 0) *mi = 0.f;
}

__global__ void k_hist(const int* __restrict__ dst) {
    int e = blockIdx.x*blockDim.x + threadIdx.x;
    if (e < EE) atomicAdd(&g_deg[dst[e]], 1);
}

__global__ void k_scan1() {
    __shared__ int s[256];
    int tid = threadIdx.x;
    int i = blockIdx.x*256 + tid;
    int v = (i < NN) ? g_deg[i] : 0;
    s[tid] = v; __syncthreads();
    for (int off = 1; off < 256; off <<= 1) {
        int t = (tid >= off) ? s[tid-off] : 0;
        __syncthreads();
        s[tid] += t;
        __syncthreads();
    }
    if (i < NN) g_rowptr[i] = s[tid] - v;  // exclusive within block
    if (tid == 255) g_bsums[blockIdx.x] = s[255];
}

__global__ void k_scan2(int nb) {
    __shared__ int s[256];
    int tid = threadIdx.x;
    int v = (tid < nb) ? g_bsums[tid] : 0;
    s[tid] = v; __syncthreads();
    for (int off = 1; off < 256; off <<= 1) {
        int t = (tid >= off) ? s[tid-off] : 0;
        __syncthreads();
        s[tid] += t;
        __syncthreads();
    }
    if (tid < nb) g_boffs[tid] = s[tid] - v;
}

__global__ void k_scan3() {
    int tid = threadIdx.x;
    int i = blockIdx.x*256 + tid;
    if (i < NN) g_rowptr[i] += g_boffs[blockIdx.x];
    if (i == 0) g_rowptr[NN] = EE;
}

__global__ void k_fill(const int* __restrict__ src, const int* __restrict__ dst,
                       const int* __restrict__ et) {
    int e = blockIdx.x*blockDim.x + threadIdx.x;
    if (e >= EE) return;
    int d = dst[e];
    int pos = g_rowptr[d] + atomicAdd(&g_cur[d], 1);
    g_csrc[pos] = src[e];
    g_cet[pos]  = et[e];
}

// ---------------- generic tiled SGEMM: C = act(A@B + bias) ------------------
// act: 0=none 1=tanh 2=leaky(0.2) 3=relu
__global__ void k_sgemm(const float* __restrict__ A, int lda,
                        const float* __restrict__ B, int ldb,
                        const float* __restrict__ bias,
                        float* __restrict__ C, int ldc,
                        int M, int N, int K, int act) {
    __shared__ float As[8][64];
    __shared__ float Bs[8][65];
    int tid = threadIdx.x;
    int tx = tid & 15, ty = tid >> 4;
    int row0 = blockIdx.x*64, col0 = blockIdx.y*64;
    float acc[4][4] = {};
    for (int k0 = 0; k0 < K; k0 += 8) {
        #pragma unroll
        for (int i = 0; i < 2; i++) {
            int idx = tid*2 + i;
            int r = idx >> 3, kk = idx & 7;
            int gr = row0 + r, gk = k0 + kk;
            As[kk][r] = (gr < M && gk < K) ? A[(size_t)gr*lda + gk] : 0.f;
        }
        #pragma unroll
        for (int i = 0; i < 2; i++) {
            int idx = tid + i*256;
            int kk = idx >> 6, c = idx & 63;
            int gc = col0 + c, gk = k0 + kk;
            Bs[kk][c] = (gk < K && gc < N) ? B[(size_t)gk*ldb + gc] : 0.f;
        }
        __syncthreads();
        #pragma unroll
        for (int kk = 0; kk < 8; kk++) {
            float a[4], b[4];
            #pragma unroll
            for (int i = 0; i < 4; i++) a[i] = As[kk][ty*4+i];
            #pragma unroll
            for (int j = 0; j < 4; j++) b[j] = Bs[kk][tx*4+j];
            #pragma unroll
            for (int i = 0; i < 4; i++)
                #pragma unroll
                for (int j = 0; j < 4; j++)
                    acc[i][j] += a[i]*b[j];
        }
        __syncthreads();
    }
    #pragma unroll
    for (int i = 0; i < 4; i++) {
        int gr = row0 + ty*4 + i;
        if (gr >= M) continue;
        #pragma unroll
        for (int j = 0; j < 4; j++) {
            int gc = col0 + tx*4 + j;
            if (gc >= N) continue;
            float v = acc[i][j] + (bias ? bias[gc] : 0.f);
            if (act == 1) v = tanhf(v);
            else if (act == 2) v = (v > 0.f) ? v : 0.2f*v;
            else if (act == 3) v = fmaxf(v, 0.f);
            C[(size_t)gr*ldc + gc] = v;
        }
    }
}

// ---------------- kw softmax over F axis ------------------------------------
__global__ void k_kwsm(const float* __restrict__ raw, float* __restrict__ kw) {
    int i = blockIdx.x*blockDim.x + threadIdx.x;
    if (i >= NN*DD) return;
    int n = i / DD, d = i - n*DD;
    const float* p = raw + (size_t)n*FD + d;
    float a0 = p[0], a1 = p[DD], a2 = p[2*DD], a3 = p[3*DD];
    float m = fmaxf(fmaxf(a0, a1), fmaxf(a2, a3));
    float e0 = __expf(a0-m), e1 = __expf(a1-m), e2 = __expf(a2-m), e3 = __expf(a3-m);
    float inv = 1.f/(e0+e1+e2+e3);
    float* q = kw + (size_t)n*FD + d;
    q[0] = e0*inv; q[DD] = e1*inv; q[2*DD] = e2*inv; q[3*DD] = e3*inv;
}

// ---------------- fused attention layer (online softmax, all F heads) -------
// block (256 thr) per dst node v; group g = tid/64 handles head g;
// lane64 owns d = lane64 + 64*j (j=0..3, guard d<200). acc & x[dst] in regs.
__global__ void k_layer(const float* __restrict__ x, const float* __restrict__ kw,
                        const float* __restrict__ r, float* __restrict__ xout) {
    int v = blockIdx.x;
    int tid = threadIdx.x;
    int g = tid >> 6;
    int lane64 = tid & 63;
    int warp = tid >> 5, lane = tid & 31;
    __shared__ float re[DD];
    __shared__ float dots[8];

    float xd[4], acc[4];
    const float* xv = x + (size_t)v*FD + g*DD;
    #pragma unroll
    for (int j = 0; j < 4; j++) {
        int d = lane64 + 64*j;
        xd[j] = (d < DD) ? xv[d] : 0.f;
        acc[j] = 0.f;
    }
    float rm = -INFINITY, rs = 0.f;

    int e0 = g_rowptr[v], e1 = g_rowptr[v+1];
    for (int e = e0; e < e1; ++e) {
        int s  = g_csrc[e];
        int et = g_cet[e];
        __syncthreads();                      // protect re/dots from prev iter
        if (tid < DD) re[tid] = r[(size_t)et*DD + tid];
        const float* xs = x + (size_t)s*FD + g*DD;
        float xsr[4];
        #pragma unroll
        for (int j = 0; j < 4; j++) {
            int d = lane64 + 64*j;
            xsr[j] = (d < DD) ? xs[d] : 0.f;
        }
        __syncthreads();                      // re ready
        float p = 0.f;
        #pragma unroll
        for (int j = 0; j < 4; j++) {
            int d = lane64 + 64*j;
            if (d < DD) p += xsr[j]*re[d]*xd[j];
        }
        #pragma unroll
        for (int o = 16; o > 0; o >>= 1) p += __shfl_down_sync(0xffffffffu, p, o);
        if (lane == 0) dots[warp] = p;
        __syncthreads();                      // dots ready
        float dot = dots[g*2] + dots[g*2+1];
        float l = (dot > 0.f) ? dot : 0.2f*dot;
        float nm = fmaxf(rm, l);
        float scale = (rm == -INFINITY) ? 0.f : __expf(rm - nm);
        float w = __expf(l - nm);
        rm = nm;
        rs = rs*scale + w;
        #pragma unroll
        for (int j = 0; j < 4; j++) {
            int d = lane64 + 64*j;
            float mv = (d < DD) ? xsr[j]*re[d] : 0.f;
            acc[j] = acc[j]*scale + w*mv;
        }
    }
    float inv = 1.f/(rs + 1e-16f);
    const float* kwv = kw + (size_t)v*FD + g*DD;
    float* ov = xout + (size_t)v*FD + g*DD;
    #pragma unroll
    for (int j = 0; j < 4; j++) {
        int d = lane64 + 64*j;
        if (d < DD) ov[d] = tanhf(acc[j]*inv) * kwv[d];
    }
}

// ---------------- output gathers --------------------------------------------
__global__ void k_subemb(const int* __restrict__ sub, const float* __restrict__ x,
                         float* __restrict__ o) {
    int b = blockIdx.x;
    int row = sub[b];
    for (int idx = threadIdx.x; idx < FD; idx += blockDim.x)
        o[(size_t)b*FD + idx] = x[(size_t)row*FD + idx];
}

__global__ void k_relemb(const int* __restrict__ rel, const float* __restrict__ ir,
                         float* __restrict__ o) {
    int b = blockIdx.x;
    int row = rel[b];
    for (int idx = threadIdx.x; idx < FD; idx += blockDim.x) {
        int d = idx % DD;
        o[(size_t)b*FD + idx] = ir[(size_t)row*DD + d];
    }
}

// ---------------- CLUB layer 1 (batched over 6 pairs x 2 nets, relu) --------
__global__ void k_club1(const float* __restrict__ semb,
                        const float* __restrict__ mu_w1, const float* __restrict__ mu_b1,
                        const float* __restrict__ lv_w1, const float* __restrict__ lv_b1,
                        float* __restrict__ H) {
    const int ci[6] = {0,0,0,1,1,2};
    int z = blockIdx.z, cnt = z >> 1, net = z & 1;
    const float* A  = semb + ci[cnt]*DD;  // lda = FD
    const float* W  = (net ? lv_w1 : mu_w1) + (size_t)cnt*DD*HH2;
    const float* bb = (net ? lv_b1 : mu_b1) + cnt*HH2;
    float* C = H + (size_t)z*BB*HH2;

    __shared__ float As[8][64];
    __shared__ float Bs[8][65];
    int tid = threadIdx.x;
    int tx = tid & 15, ty = tid >> 4;
    int row0 = blockIdx.x*64, col0 = blockIdx.y*64;
    float acc[4][4] = {};
    for (int k0 = 0; k0 < DD; k0 += 8) {
        #pragma unroll
        for (int i = 0; i < 2; i++) {
            int idx = tid*2 + i;
            int r = idx >> 3, kk = idx & 7;
            As[kk][r] = A[(size_t)(row0+r)*FD + k0 + kk];
        }
        #pragma unroll
        for (int i = 0; i < 2; i++) {
            int idx = tid + i*256;
            int kk = idx >> 6, c = idx & 63;
            int gc = col0 + c;
            Bs[kk][c] = (gc < HH2) ? W[(size_t)(k0+kk)*HH2 + gc] : 0.f;
        }
        __syncthreads();
        #pragma unroll
        for (int kk = 0; kk < 8; kk++) {
            float a[4], b[4];
            #pragma unroll
            for (int i = 0; i < 4; i++) a[i] = As[kk][ty*4+i];
            #pragma unroll
            for (int j = 0; j < 4; j++) b[j] = Bs[kk][tx*4+j];
            #pragma unroll
            for (int i = 0; i < 4; i++)
                #pragma unroll
                for (int j = 0; j < 4; j++)
                    acc[i][j] += a[i]*b[j];
        }
        __syncthreads();
    }
    #pragma unroll
    for (int i = 0; i < 4; i++) {
        int gr = row0 + ty*4 + i;
        #pragma unroll
        for (int j = 0; j < 4; j++) {
            int gc = col0 + tx*4 + j;
            if (gc < HH2)
                C[(size_t)gr*HH2 + gc] = fmaxf(acc[i][j] + bb[gc], 0.f);
        }
    }
}

// ---------------- CLUB layer 2 + loss reduction ------------------------------
__global__ void k_club2(const float* __restrict__ semb, const int* __restrict__ perm,
                        const float* __restrict__ mu_w2, const float* __restrict__ mu_b2,
                        const float* __restrict__ lv_w2, const float* __restrict__ lv_b2,
                        float* __restrict__ mi) {
    const int cj[6] = {1,2,3,2,3,3};
    int b = blockIdx.x, cnt = blockIdx.y;
    __shared__ float hm[HH2];
    __shared__ float hl[HH2];
    __shared__ float red[256];
    int tid = threadIdx.x;
    if (tid < HH2)            hm[tid]     = g_h[((size_t)(cnt*2+0)*BB + b)*HH2 + tid];
    else if (tid < 2*HH2)     hl[tid-HH2] = g_h[((size_t)(cnt*2+1)*BB + b)*HH2 + (tid-HH2)];
    __syncthreads();
    float c = 0.f;
    if (tid < DD) {
        int d = tid;
        float mu = mu_b2[cnt*DD + d];
        float lv = lv_b2[cnt*DD + d];
        const float* wm = mu_w2 + (size_t)cnt*HH2*DD + d;
        const float* wl = lv_w2 + (size_t)cnt*HH2*DD + d;
        #pragma unroll 4
        for (int h = 0; h < HH2; h++) {
            mu += hm[h]*wm[(size_t)h*DD];
            lv += hl[h]*wl[(size_t)h*DD];
        }
        lv = tanhf(lv);
        int j = cj[cnt];
        float yj  = semb[(size_t)b*FD + j*DD + d];
        float yjp = semb[(size_t)perm[b]*FD + j*DD + d];
        float d1 = mu - yj, d2 = mu - yjp;
        c = (d2*d2 - d1*d1) * expf(-lv);
    }
    red[tid] = c; __syncthreads();
    for (int o = 128; o > 0; o >>= 1) {
        if (tid < o) red[tid] += red[tid+o];
        __syncthreads();
    }
    if (tid == 0) atomicAdd(mi, red[0] * (0.5f/BB));
}

// ---------------- launch ------------------------------------------------------
extern "C" void kernel_launch(void* const* d_in, const int* in_sizes, int n_in,
                              void* d_out, int out_size) {
    const int*   sub        = (const int*)  d_in[0];
    const int*   rel        = (const int*)  d_in[1];
    const int*   eidx       = (const int*)  d_in[2];
    const int*   etype      = (const int*)  d_in[3];
    const int*   perm       = (const int*)  d_in[4];
    const float* init_embed = (const float*)d_in[5];
    const float* init_rel   = (const float*)d_in[6];
    const float* pca_w      = (const float*)d_in[7];
    const float* pca_b      = (const float*)d_in[8];
    const float* cw_w       = (const float*)d_in[9];
    const float* w_rel      = (const float*)d_in[10];
    const float* mu_w1      = (const float*)d_in[11];
    const float* mu_b1      = (const float*)d_in[12];
    const float* mu_w2      = (const float*)d_in[13];
    const float* mu_b2      = (const float*)d_in[14];
    const float* lv_w1      = (const float*)d_in[15];
    const float* lv_b1      = (const float*)d_in[16];
    const float* lv_w2      = (const float*)d_in[17];
    const float* lv_b2      = (const float*)d_in[18];
    float* out = (float*)d_out;

    const int* src = eidx;
    const int* dst = eidx + EE;

    float *xA, *xB, *kw, *r1;
    cudaGetSymbolAddress((void**)&xA, g_xA);
    cudaGetSymbolAddress((void**)&xB, g_xB);
    cudaGetSymbolAddress((void**)&kw, g_kw);
    cudaGetSymbolAddress((void**)&r1, g_r1);
    float* H;
    cudaGetSymbolAddress((void**)&H, g_h);

    const int NB = (NN + 255)/256;  // 157

    // CSR build
    k_zero<<<NB, 256>>>(out + MI_OFF);
    k_hist<<<(EE + 255)/256, 256>>>(dst);
    k_scan1<<<NB, 256>>>();
    k_scan2<<<1, 256>>>(NB);
    k_scan3<<<NB, 256>>>();
    k_fill<<<(EE + 255)/256, 256>>>(src, dst, etype);

    // x0 = tanh(init_embed @ pca_w + pca_b)  -> xA
    {
        dim3 g((NN + 63)/64, (FD + 63)/64);
        k_sgemm<<<g, 256>>>(init_embed, INITD, pca_w, FD, pca_b, xA, FD,
                            NN, FD, INITD, 1);
    }
    // kw_raw = leaky(x0.reshape(-1,D) @ cw_w)  -> xB (temp)
    {
        dim3 g((NN*FF + 63)/64, (DD + 63)/64);
        k_sgemm<<<g, 256>>>(xA, DD, cw_w, DD, nullptr, xB, DD,
                            NN*FF, DD, DD, 2);
    }
    // kw = softmax over F
    k_kwsm<<<(NN*DD + 255)/256, 256>>>(xB, kw);

    // layer 0: xA -> xB with r = init_rel
    k_layer<<<NN, 256>>>(xA, kw, init_rel, xB);

    // r1 = init_rel @ w_rel[0]
    {
        dim3 g((NRELD + 63)/64, (DD + 63)/64);
        k_sgemm<<<g, 256>>>(init_rel, DD, w_rel, DD, nullptr, r1, DD,
                            NRELD, DD, DD, 0);
    }

    // layer 1: xB -> out x region with r = r1
    k_layer<<<NN, 256>>>(xB, kw, r1, out + X_OFF);

    // sub_emb, rel_emb
    k_subemb<<<BB, 256>>>(sub, out + X_OFF, out + SUB_OFF);
    k_relemb<<<BB, 256>>>(rel, init_rel, out + REL_OFF);

    // CLUB layer 1 (12 batched GEMMs), then fused layer 2 + loss
    {
        dim3 g(BB/64, (HH2 + 63)/64, 12);
        k_club1<<<g, 256>>>(out + SUB_OFF, mu_w1, mu_b1, lv_w1, lv_b1, H);
    }
    {
        dim3 g(BB, NPAIR);
        k_club2<<<g, 256>>>(out + SUB_OFF, perm, mu_w2, mu_b2, lv_w2, lv_b2,
                            out + MI_OFF);
    }
}

// round 2
// speedup vs baseline: 1.1018x; 1.1018x over previous
#include <cuda_runtime.h>
#include <math.h>

#define NN    40000
#define INITD 100
#define DD    200
#define FF    4
#define EE    800000
#define NRELD 800
#define BB    2048
#define HH2   100
#define NPAIR 6
#define FD    (FF*DD)   // 800

// output layout: sub_emb (B,FD), rel_emb (B,FD), x (N,FD), mi_loss (1)
#define SUB_OFF 0
#define REL_OFF ((size_t)BB*FD)
#define X_OFF   ((size_t)2*BB*FD)
#define MI_OFF  ((size_t)2*BB*FD + (size_t)NN*FD)

typedef unsigned long long u64t;

// ---------------- scratch (device globals; no allocation allowed) ----------
__device__ float g_xA[(size_t)NN*FD];
__device__ float g_xB[(size_t)NN*FD];
__device__ float g_kw[(size_t)NN*FD];
__device__ float g_r1[NRELD*DD];
__device__ float g_h[12*BB*HH2];
__device__ int   g_deg[NN];
__device__ int   g_cur[NN];
__device__ int   g_rowptr[NN+1];
__device__ int   g_csrc[EE];
__device__ int   g_cet[EE];
__device__ int   g_bsums[256];
__device__ int   g_boffs[256];

// ---------------- packed f32x2 helpers --------------------------------------
__device__ __forceinline__ void ffma2(u64t& d, u64t a, u64t b) {
    asm("fma.rn.f32x2 %0, %1, %2, %0;" : "+l"(d) : "l"(a), "l"(b));
}
__device__ __forceinline__ u64t dup2(float x) {
    u64t r; asm("mov.b64 %0, {%1, %2};" : "=l"(r) : "f"(x), "f"(x)); return r;
}
__device__ __forceinline__ float2 unpack2(u64t v) {
    float lo, hi; asm("mov.b64 {%0, %1}, %2;" : "=f"(lo), "=f"(hi) : "l"(v));
    return make_float2(lo, hi);
}

// ---------------- CSR build -------------------------------------------------
__global__ void k_zero(float* mi) {
    int i = blockIdx.x*blockDim.x + threadIdx.x;
    if (i < NN) { g_deg[i] = 0; g_cur[i] = 0; }
    if (i == 0) *mi = 0.f;
}

__global__ void k_hist(const int* __restrict__ dst) {
    int e = blockIdx.x*blockDim.x + threadIdx.x;
    if (e < EE) atomicAdd(&g_deg[dst[e]], 1);
}

__global__ void k_scan1() {
    __shared__ int s[256];
    int tid = threadIdx.x;
    int i = blockIdx.x*256 + tid;
    int v = (i < NN) ? g_deg[i] : 0;
    s[tid] = v; __syncthreads();
    for (int off = 1; off < 256; off <<= 1) {
        int t = (tid >= off) ? s[tid-off] : 0;
        __syncthreads();
        s[tid] += t;
        __syncthreads();
    }
    if (i < NN) g_rowptr[i] = s[tid] - v;
    if (tid == 255) g_bsums[blockIdx.x] = s[255];
}

__global__ void k_scan2(int nb) {
    __shared__ int s[256];
    int tid = threadIdx.x;
    int v = (tid < nb) ? g_bsums[tid] : 0;
    s[tid] = v; __syncthreads();
    for (int off = 1; off < 256; off <<= 1) {
        int t = (tid >= off) ? s[tid-off] : 0;
        __syncthreads();
        s[tid] += t;
        __syncthreads();
    }
    if (tid < nb) g_boffs[tid] = s[tid] - v;
}

__global__ void k_scan3() {
    int tid = threadIdx.x;
    int i = blockIdx.x*256 + tid;
    if (i < NN) g_rowptr[i] += g_boffs[blockIdx.x];
    if (i == 0) g_rowptr[NN] = EE;
}

__global__ void k_fill(const int* __restrict__ src, const int* __restrict__ dst,
                       const int* __restrict__ et) {
    int e = blockIdx.x*blockDim.x + threadIdx.x;
    if (e >= EE) return;
    int d = dst[e];
    int pos = g_rowptr[d] + atomicAdd(&g_cur[d], 1);
    g_csrc[pos] = src[e];
    g_cet[pos]  = et[e];
}

// ---------------- SGEMM v2: 128x64 tile, KT=16, f32x2 packed FMA ------------
// act: 0=none 1=tanh 2=leaky(0.2) 3=relu
__global__ void k_sgemm2(const float* __restrict__ A, int lda,
                         const float* __restrict__ B, int ldb,
                         const float* __restrict__ bias,
                         float* __restrict__ C, int ldc,
                         int M, int N, int K, int act) {
    __shared__ __align__(16) float As[16][128];
    __shared__ __align__(16) float Bs[16][64];
    int tid = threadIdx.x;
    int tx = tid & 15, ty = tid >> 4;
    int row0 = blockIdx.x*128, col0 = blockIdx.y*64;

    u64t acc[4][4];
    #pragma unroll
    for (int i = 0; i < 4; i++)
        #pragma unroll
        for (int j = 0; j < 4; j++) acc[i][j] = 0ull;

    int ar  = tid >> 1;          // 0..127 (A row within tile)
    int akq = (tid & 1) * 8;     // k quad base 0 or 8
    int bk  = tid >> 4;          // 0..15  (B k within tile)
    int bc  = (tid & 15) * 4;    // B col quad

    for (int k0 = 0; k0 < K; k0 += 16) {
        // --- A tile load ---
        if ((k0 + 16 <= K) && (row0 + 128 <= M)) {
            const float* ap = A + (size_t)(row0 + ar)*lda + k0 + akq;
            float4 v0 = *(const float4*)ap;
            float4 v1 = *(const float4*)(ap + 4);
            As[akq+0][ar] = v0.x; As[akq+1][ar] = v0.y;
            As[akq+2][ar] = v0.z; As[akq+3][ar] = v0.w;
            As[akq+4][ar] = v1.x; As[akq+5][ar] = v1.y;
            As[akq+6][ar] = v1.z; As[akq+7][ar] = v1.w;
        } else {
            int gr = row0 + ar;
            #pragma unroll
            for (int c = 0; c < 8; c++) {
                int gk = k0 + akq + c;
                As[akq+c][ar] = (gr < M && gk < K) ? A[(size_t)gr*lda + gk] : 0.f;
            }
        }
        // --- B tile load ---
        if ((k0 + 16 <= K) && (col0 + 64 <= N)) {
            float4 v = *(const float4*)(B + (size_t)(k0 + bk)*ldb + col0 + bc);
            *(float4*)&Bs[bk][bc] = v;
        } else {
            int gk = k0 + bk;
            #pragma unroll
            for (int c = 0; c < 4; c++) {
                int gc = col0 + bc + c;
                Bs[bk][bc+c] = (gk < K && gc < N) ? B[(size_t)gk*ldb + gc] : 0.f;
            }
        }
        __syncthreads();
        #pragma unroll
        for (int kk = 0; kk < 16; kk++) {
            const ulonglong2* ap2 = (const ulonglong2*)&As[kk][ty*8];
            ulonglong2 aA = ap2[0];   // rows +0,+1 / +2,+3
            ulonglong2 aB = ap2[1];   // rows +4,+5 / +6,+7
            float4 bv = *(const float4*)&Bs[kk][tx*4];
            u64t b0 = dup2(bv.x), b1 = dup2(bv.y), b2 = dup2(bv.z), b3 = dup2(bv.w);
            ffma2(acc[0][0], aA.x, b0); ffma2(acc[0][1], aA.x, b1);
            ffma2(acc[0][2], aA.x, b2); ffma2(acc[0][3], aA.x, b3);
            ffma2(acc[1][0], aA.y, b0); ffma2(acc[1][1], aA.y, b1);
            ffma2(acc[1][2], aA.y, b2); ffma2(acc[1][3], aA.y, b3);
            ffma2(acc[2][0], aB.x, b0); ffma2(acc[2][1], aB.x, b1);
            ffma2(acc[2][2], aB.x, b2); ffma2(acc[2][3], aB.x, b3);
            ffma2(acc[3][0], aB.y, b0); ffma2(acc[3][1], aB.y, b1);
            ffma2(acc[3][2], aB.y, b2); ffma2(acc[3][3], aB.y, b3);
        }
        __syncthreads();
    }

    // --- epilogue ---
    #pragma unroll
    for (int i2 = 0; i2 < 4; i2++) {
        int r0 = row0 + ty*8 + i2*2;
        #pragma unroll
        for (int j = 0; j < 4; j++) {
            int gc = col0 + tx*4 + j;
            if (gc >= N) continue;
            float2 p = unpack2(acc[i2][j]);
            float bv = bias ? bias[gc] : 0.f;
            float v0 = p.x + bv, v1 = p.y + bv;
            if (act == 1) { v0 = tanhf(v0); v1 = tanhf(v1); }
            else if (act == 2) { v0 = (v0 > 0.f) ? v0 : 0.2f*v0; v1 = (v1 > 0.f) ? v1 : 0.2f*v1; }
            else if (act == 3) { v0 = fmaxf(v0, 0.f); v1 = fmaxf(v1, 0.f); }
            if (r0     < M) C[(size_t)r0    *ldc + gc] = v0;
            if (r0 + 1 < M) C[(size_t)(r0+1)*ldc + gc] = v1;
        }
    }
}

// ---------------- kw softmax over F axis ------------------------------------
__global__ void k_kwsm(const float* __restrict__ raw, float* __restrict__ kw) {
    int i = blockIdx.x*blockDim.x + threadIdx.x;
    if (i >= NN*DD) return;
    int n = i / DD, d = i - n*DD;
    const float* p = raw + (size_t)n*FD + d;
    float a0 = p[0], a1 = p[DD], a2 = p[2*DD], a3 = p[3*DD];
    float m = fmaxf(fmaxf(a0, a1), fmaxf(a2, a3));
    float e0 = __expf(a0-m), e1 = __expf(a1-m), e2 = __expf(a2-m), e3 = __expf(a3-m);
    float inv = 1.f/(e0+e1+e2+e3);
    float* q = kw + (size_t)n*FD + d;
    q[0] = e0*inv; q[DD] = e1*inv; q[2*DD] = e2*inv; q[3*DD] = e3*inv;
}

// ---------------- fused attention layer, chunk-of-4 edges -------------------
// block (256 thr) per dst node v; group g = tid/64 handles head g.
__global__ void k_layer(const float* __restrict__ x, const float* __restrict__ kw,
                        const float* __restrict__ r, float* __restrict__ xout) {
    int v = blockIdx.x;
    int tid = threadIdx.x;
    int g = tid >> 6;
    int lane64 = tid & 63;
    int warp = tid >> 5, lane = tid & 31;
    __shared__ float re[4][DD];
    __shared__ float dots[8][4];

    float xd[4], acc[4];
    const float* xv = x + (size_t)v*FD + g*DD;
    #pragma unroll
    for (int j = 0; j < 4; j++) {
        int d = lane64 + 64*j;
        xd[j] = (d < DD) ? xv[d] : 0.f;
        acc[j] = 0.f;
    }
    float rm = -INFINITY, rs = 0.f;

    int e0 = g_rowptr[v], e1 = g_rowptr[v+1];
    for (int eb = e0; eb < e1; eb += 4) {
        int m = min(4, e1 - eb);
        __syncthreads();                      // protect re/dots from prev chunk
        for (int idx = tid; idx < m*DD; idx += 256) {
            int c = idx / DD, d = idx - c*DD;
            re[c][d] = r[(size_t)g_cet[eb+c]*DD + d];
        }
        float xsr[4][4];
        #pragma unroll
        for (int c = 0; c < 4; c++) {
            if (c < m) {
                int s = g_csrc[eb+c];
                const float* xs = x + (size_t)s*FD + g*DD;
                #pragma unroll
                for (int j = 0; j < 4; j++) {
                    int d = lane64 + 64*j;
                    xsr[c][j] = (d < DD) ? xs[d] : 0.f;
                }
            }
        }
        __syncthreads();                      // re ready
        #pragma unroll
        for (int c = 0; c < 4; c++) {
            if (c >= m) break;
            float p = 0.f;
            #pragma unroll
            for (int j = 0; j < 4; j++) {
                int d = lane64 + 64*j;
                if (d < DD) p += xsr[c][j]*re[c][d]*xd[j];
            }
            #pragma unroll
            for (int o = 16; o > 0; o >>= 1) p += __shfl_down_sync(0xffffffffu, p, o);
            if (lane == 0) dots[warp][c] = p;
        }
        __syncthreads();                      // dots ready
        #pragma unroll
        for (int c = 0; c < 4; c++) {
            if (c >= m) break;
            float dot = dots[g*2][c] + dots[g*2+1][c];
            float l = (dot > 0.f) ? dot : 0.2f*dot;
            float nm = fmaxf(rm, l);
            float scale = (rm == -INFINITY) ? 0.f : __expf(rm - nm);
            float w = __expf(l - nm);
            rm = nm;
            rs = rs*scale + w;
            #pragma unroll
            for (int j = 0; j < 4; j++) {
                int d = lane64 + 64*j;
                float mv = (d < DD) ? xsr[c][j]*re[c][d] : 0.f;
                acc[j] = acc[j]*scale + w*mv;
            }
        }
    }
    float inv = 1.f/(rs + 1e-16f);
    const float* kwv = kw + (size_t)v*FD + g*DD;
    float* ov = xout + (size_t)v*FD + g*DD;
    #pragma unroll
    for (int j = 0; j < 4; j++) {
        int d = lane64 + 64*j;
        if (d < DD) ov[d] = tanhf(acc[j]*inv) * kwv[d];
    }
}

// ---------------- output gathers --------------------------------------------
__global__ void k_subemb(const int* __restrict__ sub, const float* __restrict__ x,
                         float* __restrict__ o) {
    int b = blockIdx.x;
    int row = sub[b];
    for (int idx = threadIdx.x; idx < FD; idx += blockDim.x)
        o[(size_t)b*FD + idx] = x[(size_t)row*FD + idx];
}

__global__ void k_relemb(const int* __restrict__ rel, const float* __restrict__ ir,
                         float* __restrict__ o) {
    int b = blockIdx.x;
    int row = rel[b];
    for (int idx = threadIdx.x; idx < FD; idx += blockDim.x) {
        int d = idx % DD;
        o[(size_t)b*FD + idx] = ir[(size_t)row*DD + d];
    }
}

// ---------------- CLUB layer 1 (batched over 6 pairs x 2 nets, relu) --------
__global__ void k_club1(const float* __restrict__ semb,
                        const float* __restrict__ mu_w1, const float* __restrict__ mu_b1,
                        const float* __restrict__ lv_w1, const float* __restrict__ lv_b1,
                        float* __restrict__ H) {
    const int ci[6] = {0,0,0,1,1,2};
    int z = blockIdx.z, cnt = z >> 1, net = z & 1;
    const float* A  = semb + ci[cnt]*DD;  // lda = FD
    const float* W  = (net ? lv_w1 : mu_w1) + (size_t)cnt*DD*HH2;
    const float* bb = (net ? lv_b1 : mu_b1) + cnt*HH2;
    float* C = H + (size_t)z*BB*HH2;

    __shared__ float As[8][64];
    __shared__ float Bs[8][65];
    int tid = threadIdx.x;
    int tx = tid & 15, ty = tid >> 4;
    int row0 = blockIdx.x*64, col0 = blockIdx.y*64;
    float acc[4][4] = {};
    for (int k0 = 0; k0 < DD; k0 += 8) {
        #pragma unroll
        for (int i = 0; i < 2; i++) {
            int idx = tid*2 + i;
            int r = idx >> 3, kk = idx & 7;
            As[kk][r] = A[(size_t)(row0+r)*FD + k0 + kk];
        }
        #pragma unroll
        for (int i = 0; i < 2; i++) {
            int idx = tid + i*256;
            int kk = idx >> 6, c = idx & 63;
            int gc = col0 + c;
            Bs[kk][c] = (gc < HH2) ? W[(size_t)(k0+kk)*HH2 + gc] : 0.f;
        }
        __syncthreads();
        #pragma unroll
        for (int kk = 0; kk < 8; kk++) {
            float a[4], b[4];
            #pragma unroll
            for (int i = 0; i < 4; i++) a[i] = As[kk][ty*4+i];
            #pragma unroll
            for (int j = 0; j < 4; j++) b[j] = Bs[kk][tx*4+j];
            #pragma unroll
            for (int i = 0; i < 4; i++)
                #pragma unroll
                for (int j = 0; j < 4; j++)
                    acc[i][j] += a[i]*b[j];
        }
        __syncthreads();
    }
    #pragma unroll
    for (int i = 0; i < 4; i++) {
        int gr = row0 + ty*4 + i;
        #pragma unroll
        for (int j = 0; j < 4; j++) {
            int gc = col0 + tx*4 + j;
            if (gc < HH2)
                C[(size_t)gr*HH2 + gc] = fmaxf(acc[i][j] + bb[gc], 0.f);
        }
    }
}

// ---------------- CLUB layer 2 + loss reduction ------------------------------
__global__ void k_club2(const float* __restrict__ semb, const int* __restrict__ perm,
                        const float* __restrict__ mu_w2, const float* __restrict__ mu_b2,
                        const float* __restrict__ lv_w2, const float* __restrict__ lv_b2,
                        float* __restrict__ mi) {
    const int cj[6] = {1,2,3,2,3,3};
    int b = blockIdx.x, cnt = blockIdx.y;
    __shared__ float hm[HH2];
    __shared__ float hl[HH2];
    __shared__ float red[256];
    int tid = threadIdx.x;
    if (tid < HH2)            hm[tid]     = g_h[((size_t)(cnt*2+0)*BB + b)*HH2 + tid];
    else if (tid < 2*HH2)     hl[tid-HH2] = g_h[((size_t)(cnt*2+1)*BB + b)*HH2 + (tid-HH2)];
    __syncthreads();
    float c = 0.f;
    if (tid < DD) {
        int d = tid;
        float mu = mu_b2[cnt*DD + d];
        float lv = lv_b2[cnt*DD + d];
        const float* wm = mu_w2 + (size_t)cnt*HH2*DD + d;
        const float* wl = lv_w2 + (size_t)cnt*HH2*DD + d;
        #pragma unroll 4
        for (int h = 0; h < HH2; h++) {
            mu += hm[h]*wm[(size_t)h*DD];
            lv += hl[h]*wl[(size_t)h*DD];
        }
        lv = tanhf(lv);
        int j = cj[cnt];
        float yj  = semb[(size_t)b*FD + j*DD + d];
        float yjp = semb[(size_t)perm[b]*FD + j*DD + d];
        float d1 = mu - yj, d2 = mu - yjp;
        c = (d2*d2 - d1*d1) * expf(-lv);
    }
    red[tid] = c; __syncthreads();
    for (int o = 128; o > 0; o >>= 1) {
        if (tid < o) red[tid] += red[tid+o];
        __syncthreads();
    }
    if (tid == 0) atomicAdd(mi, red[0] * (0.5f/BB));
}

// ---------------- launch ------------------------------------------------------
extern "C" void kernel_launch(void* const* d_in, const int* in_sizes, int n_in,
                              void* d_out, int out_size) {
    const int*   sub        = (const int*)  d_in[0];
    const int*   rel        = (const int*)  d_in[1];
    const int*   eidx       = (const int*)  d_in[2];
    const int*   etype      = (const int*)  d_in[3];
    const int*   perm       = (const int*)  d_in[4];
    const float* init_embed = (const float*)d_in[5];
    const float* init_rel   = (const float*)d_in[6];
    const float* pca_w      = (const float*)d_in[7];
    const float* pca_b      = (const float*)d_in[8];
    const float* cw_w       = (const float*)d_in[9];
    const float* w_rel      = (const float*)d_in[10];
    const float* mu_w1      = (const float*)d_in[11];
    const float* mu_b1      = (const float*)d_in[12];
    const float* mu_w2      = (const float*)d_in[13];
    const float* mu_b2      = (const float*)d_in[14];
    const float* lv_w1      = (const float*)d_in[15];
    const float* lv_b1      = (const float*)d_in[16];
    const float* lv_w2      = (const float*)d_in[17];
    const float* lv_b2      = (const float*)d_in[18];
    float* out = (float*)d_out;

    const int* src = eidx;
    const int* dst = eidx + EE;

    float *xA, *xB, *kw, *r1;
    cudaGetSymbolAddress((void**)&xA, g_xA);
    cudaGetSymbolAddress((void**)&xB, g_xB);
    cudaGetSymbolAddress((void**)&kw, g_kw);
    cudaGetSymbolAddress((void**)&r1, g_r1);
    float* H;
    cudaGetSymbolAddress((void**)&H, g_h);

    const int NB = (NN + 255)/256;  // 157

    // CSR build
    k_zero<<<NB, 256>>>(out + MI_OFF);
    k_hist<<<(EE + 255)/256, 256>>>(dst);
    k_scan1<<<NB, 256>>>();
    k_scan2<<<1, 256>>>(NB);
    k_scan3<<<NB, 256>>>();
    k_fill<<<(EE + 255)/256, 256>>>(src, dst, etype);

    // x0 = tanh(init_embed @ pca_w + pca_b)  -> xA
    {
        dim3 g((NN + 127)/128, (FD + 63)/64);
        k_sgemm2<<<g, 256>>>(init_embed, INITD, pca_w, FD, pca_b, xA, FD,
                             NN, FD, INITD, 1);
    }
    // kw_raw = leaky(x0.reshape(-1,D) @ cw_w)  -> xB (temp)
    {
        dim3 g((NN*FF + 127)/128, (DD + 63)/64);
        k_sgemm2<<<g, 256>>>(xA, DD, cw_w, DD, nullptr, xB, DD,
                             NN*FF, DD, DD, 2);
    }
    // kw = softmax over F
    k_kwsm<<<(NN*DD + 255)/256, 256>>>(xB, kw);

    // layer 0: xA -> xB with r = init_rel
    k_layer<<<NN, 256>>>(xA, kw, init_rel, xB);

    // r1 = init_rel @ w_rel[0]
    {
        dim3 g((NRELD + 127)/128, (DD + 63)/64);
        k_sgemm2<<<g, 256>>>(init_rel, DD, w_rel, DD, nullptr, r1, DD,
                             NRELD, DD, DD, 0);
    }

    // layer 1: xB -> out x region with r = r1
    k_layer<<<NN, 256>>>(xB, kw, r1, out + X_OFF);

    // sub_emb, rel_emb
    k_subemb<<<BB, 256>>>(sub, out + X_OFF, out + SUB_OFF);
    k_relemb<<<BB, 256>>>(rel, init_rel, out + REL_OFF);

    // CLUB layer 1 (12 batched GEMMs), then fused layer 2 + loss
    {
        dim3 g(BB/64, (HH2 + 63)/64, 12);
        k_club1<<<g, 256>>>(out + SUB_OFF, mu_w1, mu_b1, lv_w1, lv_b1, H);
    }
    {
        dim3 g(BB, NPAIR);
        k_club2<<<g, 256>>>(out + SUB_OFF, perm, mu_w2, mu_b2, lv_w2, lv_b2,
                            out + MI_OFF);
    }
}

// round 3
// speedup vs baseline: 1.2275x; 1.1141x over previous
#include <cuda_runtime.h>
#include <math.h>

#define NN    40000
#define INITD 100
#define DD    200
#define FF    4
#define EE    800000
#define NRELD 800
#define BB    2048
#define HH2   100
#define NPAIR 6
#define FD    (FF*DD)   // 800

// output layout: sub_emb (B,FD), rel_emb (B,FD), x (N,FD), mi_loss (1)
#define SUB_OFF 0
#define REL_OFF ((size_t)BB*FD)
#define X_OFF   ((size_t)2*BB*FD)
#define MI_OFF  ((size_t)2*BB*FD + (size_t)NN*FD)

typedef unsigned long long u64t;

// ---------------- scratch (device globals; no allocation allowed) ----------
__device__ float g_xA[(size_t)NN*FD];   // head-major [F][N][D]
__device__ float g_xB[(size_t)NN*FD];   // head-major [F][N][D]
__device__ float g_kw[(size_t)NN*FD];   // head-major [F][N][D]
__device__ float g_r1[NRELD*DD];
__device__ float g_h[12*BB*HH2];
__device__ int   g_deg[NN];
__device__ int   g_cur[NN];
__device__ int   g_rowptr[NN+1];
__device__ int   g_csrc[EE];
__device__ int   g_cet[EE];
__device__ int   g_bsums[256];
__device__ int   g_boffs[256];

// ---------------- packed f32x2 helpers --------------------------------------
__device__ __forceinline__ void ffma2(u64t& d, u64t a, u64t b) {
    asm("fma.rn.f32x2 %0, %1, %2, %0;" : "+l"(d) : "l"(a), "l"(b));
}
__device__ __forceinline__ u64t dup2(float x) {
    u64t r; asm("mov.b64 %0, {%1, %2};" : "=l"(r) : "f"(x), "f"(x)); return r;
}
__device__ __forceinline__ float2 unpack2(u64t v) {
    float lo, hi; asm("mov.b64 {%0, %1}, %2;" : "=f"(lo), "=f"(hi) : "l"(v));
    return make_float2(lo, hi);
}

// ---------------- CSR build -------------------------------------------------
__global__ void k_zero(float* mi) {
    int i = blockIdx.x*blockDim.x + threadIdx.x;
    if (i < NN) { g_deg[i] = 0; g_cur[i] = 0; }
    if (i == 0) *mi = 0.f;
}

__global__ void k_hist(const int* __restrict__ dst) {
    int e = blockIdx.x*blockDim.x + threadIdx.x;
    if (e < EE) atomicAdd(&g_deg[dst[e]], 1);
}

__global__ void k_scan1() {
    __shared__ int s[256];
    int tid = threadIdx.x;
    int i = blockIdx.x*256 + tid;
    int v = (i < NN) ? g_deg[i] : 0;
    s[tid] = v; __syncthreads();
    for (int off = 1; off < 256; off <<= 1) {
        int t = (tid >= off) ? s[tid-off] : 0;
        __syncthreads();
        s[tid] += t;
        __syncthreads();
    }
    if (i < NN) g_rowptr[i] = s[tid] - v;
    if (tid == 255) g_bsums[blockIdx.x] = s[255];
}

__global__ void k_scan2(int nb) {
    __shared__ int s[256];
    int tid = threadIdx.x;
    int v = (tid < nb) ? g_bsums[tid] : 0;
    s[tid] = v; __syncthreads();
    for (int off = 1; off < 256; off <<= 1) {
        int t = (tid >= off) ? s[tid-off] : 0;
        __syncthreads();
        s[tid] += t;
        __syncthreads();
    }
    if (tid < nb) g_boffs[tid] = s[tid] - v;
}

__global__ void k_scan3() {
    int tid = threadIdx.x;
    int i = blockIdx.x*256 + tid;
    if (i < NN) g_rowptr[i] += g_boffs[blockIdx.x];
    if (i == 0) g_rowptr[NN] = EE;
}

__global__ void k_fill(const int* __restrict__ src, const int* __restrict__ dst,
                       const int* __restrict__ et) {
    int e = blockIdx.x*blockDim.x + threadIdx.x;
    if (e >= EE) return;
    int d = dst[e];
    int pos = g_rowptr[d] + atomicAdd(&g_cur[d], 1);
    g_csrc[pos] = src[e];
    g_cet[pos]  = et[e];
}

// ---------------- SGEMM v3: 128x64 tile, 8x8 micro, 128 thr, f32x2 ----------
// act: 0=none 1=tanh 2=leaky(0.2) 3=relu
// hm:  head-major store of C: col gc -> (f = gc/DD, d = gc%DD), idx f*NN*DD + row*DD + d
__global__ void k_sgemm3(const float* __restrict__ A, int lda,
                         const float* __restrict__ B, int ldb,
                         const float* __restrict__ bias,
                         float* __restrict__ C, int ldc,
                         int M, int N, int K, int act, int hm) {
    __shared__ __align__(16) float As[16][128];
    __shared__ __align__(16) float Bs[16][64];
    int tid = threadIdx.x;
    int tx = tid & 7, ty = tid >> 3;          // 8 x 16 thread grid
    int row0 = blockIdx.x*128, col0 = blockIdx.y*64;

    u64t acc[4][8];
    #pragma unroll
    for (int i = 0; i < 4; i++)
        #pragma unroll
        for (int j = 0; j < 8; j++) acc[i][j] = 0ull;

    int ar = tid;                 // A row within tile (0..127), loads 16 k's
    int bk = tid >> 3;            // B k row (0..15)
    int bc = (tid & 7) * 8;       // B col base

    for (int k0 = 0; k0 < K; k0 += 16) {
        // --- A tile ---
        if ((k0 + 16 <= K) && (row0 + 128 <= M)) {
            const float* ap = A + (size_t)(row0 + ar)*lda + k0;
            float4 v0 = *(const float4*)(ap);
            float4 v1 = *(const float4*)(ap + 4);
            float4 v2 = *(const float4*)(ap + 8);
            float4 v3 = *(const float4*)(ap + 12);
            As[0][ar]=v0.x;  As[1][ar]=v0.y;  As[2][ar]=v0.z;  As[3][ar]=v0.w;
            As[4][ar]=v1.x;  As[5][ar]=v1.y;  As[6][ar]=v1.z;  As[7][ar]=v1.w;
            As[8][ar]=v2.x;  As[9][ar]=v2.y;  As[10][ar]=v2.z; As[11][ar]=v2.w;
            As[12][ar]=v3.x; As[13][ar]=v3.y; As[14][ar]=v3.z; As[15][ar]=v3.w;
        } else {
            int gr = row0 + ar;
            #pragma unroll
            for (int c = 0; c < 16; c++) {
                int gk = k0 + c;
                As[c][ar] = (gr < M && gk < K) ? A[(size_t)gr*lda + gk] : 0.f;
            }
        }
        // --- B tile ---
        if ((k0 + 16 <= K) && (col0 + 64 <= N)) {
            const float* bp = B + (size_t)(k0 + bk)*ldb + col0 + bc;
            *(float4*)&Bs[bk][bc]   = *(const float4*)bp;
            *(float4*)&Bs[bk][bc+4] = *(const float4*)(bp + 4);
        } else {
            int gk = k0 + bk;
            #pragma unroll
            for (int c = 0; c < 8; c++) {
                int gc = col0 + bc + c;
                Bs[bk][bc+c] = (gk < K && gc < N) ? B[(size_t)gk*ldb + gc] : 0.f;
            }
        }
        __syncthreads();
        #pragma unroll
        for (int kk = 0; kk < 16; kk++) {
            const ulonglong2* ap2 = (const ulonglong2*)&As[kk][ty*8];
            ulonglong2 aA = ap2[0];   // row pairs (0,1),(2,3)
            ulonglong2 aB = ap2[1];   // row pairs (4,5),(6,7)
            float4 bv0 = *(const float4*)&Bs[kk][tx*8];
            float4 bv1 = *(const float4*)&Bs[kk][tx*8+4];
            u64t b[8];
            b[0]=dup2(bv0.x); b[1]=dup2(bv0.y); b[2]=dup2(bv0.z); b[3]=dup2(bv0.w);
            b[4]=dup2(bv1.x); b[5]=dup2(bv1.y); b[6]=dup2(bv1.z); b[7]=dup2(bv1.w);
            #pragma unroll
            for (int j = 0; j < 8; j++) {
                ffma2(acc[0][j], aA.x, b[j]);
                ffma2(acc[1][j], aA.y, b[j]);
                ffma2(acc[2][j], aB.x, b[j]);
                ffma2(acc[3][j], aB.y, b[j]);
            }
        }
        __syncthreads();
    }

    // --- epilogue ---
    #pragma unroll
    for (int i = 0; i < 4; i++) {
        int r0 = row0 + ty*8 + i*2;
        #pragma unroll
        for (int j = 0; j < 8; j++) {
            int gc = col0 + tx*8 + j;
            if (gc >= N) continue;
            float2 p = unpack2(acc[i][j]);
            float bv = bias ? bias[gc] : 0.f;
            float v0 = p.x + bv, v1 = p.y + bv;
            if (act == 1) { v0 = tanhf(v0); v1 = tanhf(v1); }
            else if (act == 2) { v0 = (v0 > 0.f) ? v0 : 0.2f*v0; v1 = (v1 > 0.f) ? v1 : 0.2f*v1; }
            else if (act == 3) { v0 = fmaxf(v0, 0.f); v1 = fmaxf(v1, 0.f); }
            if (hm) {
                int f = gc / DD, d = gc - f*DD;
                size_t base = (size_t)f*NN*DD + d;
                if (r0     < M) C[base + (size_t)r0    *DD] = v0;
                if (r0 + 1 < M) C[base + (size_t)(r0+1)*DD] = v1;
            } else {
                if (r0     < M) C[(size_t)r0    *ldc + gc] = v0;
                if (r0 + 1 < M) C[(size_t)(r0+1)*ldc + gc] = v1;
            }
        }
    }
}

// ---------------- kw softmax over F axis (head-major layout) ----------------
__global__ void k_kwsm(const float* __restrict__ raw, float* __restrict__ kw) {
    int i = blockIdx.x*blockDim.x + threadIdx.x;
    if (i >= NN*DD) return;
    const float* p = raw + i;
    const size_t S = (size_t)NN*DD;
    float a0 = p[0], a1 = p[S], a2 = p[2*S], a3 = p[3*S];
    float m = fmaxf(fmaxf(a0, a1), fmaxf(a2, a3));
    float e0 = __expf(a0-m), e1 = __expf(a1-m), e2 = __expf(a2-m), e3 = __expf(a3-m);
    float inv = 1.f/(e0+e1+e2+e3);
    float* q = kw + i;
    q[0] = e0*inv; q[S] = e1*inv; q[2*S] = e2*inv; q[3*S] = e3*inv;
}

// ---------------- attention layer: warp per node, 2 heads per pass ----------
// x, kw head-major. hb = head base (0 or 2). ilv: interleaved (N,FD) output.
__global__ void k_layer2h(const float* __restrict__ x, const float* __restrict__ kw,
                          const float* __restrict__ r, float* __restrict__ xout,
                          int hb, int ilv) {
    int warp = threadIdx.x >> 5, lane = threadIdx.x & 31;
    int v = blockIdx.x*8 + warp;
    const float* X0 = x + (size_t)hb    *NN*DD;
    const float* X1 = x + (size_t)(hb+1)*NN*DD;

    float xd0[7], xd1[7], acc0[7], acc1[7];
    #pragma unroll
    for (int j = 0; j < 7; j++) {
        int d = lane + 32*j;
        bool ok = d < DD;
        xd0[j] = ok ? X0[(size_t)v*DD + d] : 0.f;
        xd1[j] = ok ? X1[(size_t)v*DD + d] : 0.f;
        acc0[j] = 0.f; acc1[j] = 0.f;
    }
    float rm0 = -INFINITY, rs0 = 0.f, rm1 = -INFINITY, rs1 = 0.f;

    int e0 = g_rowptr[v], e1 = g_rowptr[v+1];
    for (int eb = e0; eb < e1; eb += 2) {
        int m = min(2, e1 - eb);
        float xs0[2][7], xs1[2][7], rr[2][7], p0[2], p1[2];
        #pragma unroll
        for (int c = 0; c < 2; c++) {
            if (c >= m) { p0[c] = 0.f; p1[c] = 0.f; continue; }
            int s  = g_csrc[eb+c];
            int et = g_cet[eb+c];
            const float* rp = r + (size_t)et*DD;
            const float* xp0 = X0 + (size_t)s*DD;
            const float* xp1 = X1 + (size_t)s*DD;
            float a0 = 0.f, a1 = 0.f;
            #pragma unroll
            for (int j = 0; j < 7; j++) {
                int d = lane + 32*j;
                bool ok = d < DD;
                float xv0 = ok ? xp0[d] : 0.f;
                float xv1 = ok ? xp1[d] : 0.f;
                float rv  = ok ? rp[d]  : 0.f;
                xs0[c][j] = xv0; xs1[c][j] = xv1; rr[c][j] = rv;
                a0 += xv0*rv*xd0[j];
                a1 += xv1*rv*xd1[j];
            }
            p0[c] = a0; p1[c] = a1;
        }
        #pragma unroll
        for (int o = 16; o > 0; o >>= 1) {
            p0[0] += __shfl_xor_sync(0xffffffffu, p0[0], o);
            p0[1] += __shfl_xor_sync(0xffffffffu, p0[1], o);
            p1[0] += __shfl_xor_sync(0xffffffffu, p1[0], o);
            p1[1] += __shfl_xor_sync(0xffffffffu, p1[1], o);
        }
        #pragma unroll
        for (int c = 0; c < 2; c++) {
            if (c >= m) break;
            {
                float dot = p0[c];
                float l = (dot > 0.f) ? dot : 0.2f*dot;
                float nm = fmaxf(rm0, l);
                float sc = (rm0 == -INFINITY) ? 0.f : __expf(rm0 - nm);
                float w = __expf(l - nm);
                rm0 = nm; rs0 = rs0*sc + w;
                #pragma unroll
                for (int j = 0; j < 7; j++)
                    acc0[j] = acc0[j]*sc + w*(xs0[c][j]*rr[c][j]);
            }
            {
                float dot = p1[c];
                float l = (dot > 0.f) ? dot : 0.2f*dot;
                float nm = fmaxf(rm1, l);
                float sc = (rm1 == -INFINITY) ? 0.f : __expf(rm1 - nm);
                float w = __expf(l - nm);
                rm1 = nm; rs1 = rs1*sc + w;
                #pragma unroll
                for (int j = 0; j < 7; j++)
                    acc1[j] = acc1[j]*sc + w*(xs1[c][j]*rr[c][j]);
            }
        }
    }
    float inv0 = 1.f/(rs0 + 1e-16f);
    float inv1 = 1.f/(rs1 + 1e-16f);
    const float* kw0 = kw + ((size_t)hb    *NN + v)*DD;
    const float* kw1 = kw + ((size_t)(hb+1)*NN + v)*DD;
    #pragma unroll
    for (int j = 0; j < 7; j++) {
        int d = lane + 32*j;
        if (d >= DD) break;
        float o0 = tanhf(acc0[j]*inv0) * kw0[d];
        float o1 = tanhf(acc1[j]*inv1) * kw1[d];
        if (ilv) {
            xout[(size_t)v*FD + (size_t)hb    *DD + d] = o0;
            xout[(size_t)v*FD + (size_t)(hb+1)*DD + d] = o1;
        } else {
            xout[((size_t)hb    *NN + v)*DD + d] = o0;
            xout[((size_t)(hb+1)*NN + v)*DD + d] = o1;
        }
    }
}

// ---------------- output gathers --------------------------------------------
__global__ void k_subemb(const int* __restrict__ sub, const float* __restrict__ x,
                         float* __restrict__ o) {
    int b = blockIdx.x;
    int row = sub[b];
    for (int idx = threadIdx.x; idx < FD; idx += blockDim.x)
        o[(size_t)b*FD + idx] = x[(size_t)row*FD + idx];
}

__global__ void k_relemb(const int* __restrict__ rel, const float* __restrict__ ir,
                         float* __restrict__ o) {
    int b = blockIdx.x;
    int row = rel[b];
    for (int idx = threadIdx.x; idx < FD; idx += blockDim.x) {
        int d = idx % DD;
        o[(size_t)b*FD + idx] = ir[(size_t)row*DD + d];
    }
}

// ---------------- CLUB layer 1 (batched over 6 pairs x 2 nets, relu) --------
__global__ void k_club1(const float* __restrict__ semb,
                        const float* __restrict__ mu_w1, const float* __restrict__ mu_b1,
                        const float* __restrict__ lv_w1, const float* __restrict__ lv_b1,
                        float* __restrict__ H) {
    const int ci[6] = {0,0,0,1,1,2};
    int z = blockIdx.z, cnt = z >> 1, net = z & 1;
    const float* A  = semb + ci[cnt]*DD;  // lda = FD
    const float* W  = (net ? lv_w1 : mu_w1) + (size_t)cnt*DD*HH2;
    const float* bb = (net ? lv_b1 : mu_b1) + cnt*HH2;
    float* C = H + (size_t)z*BB*HH2;

    __shared__ float As[8][64];
    __shared__ float Bs[8][65];
    int tid = threadIdx.x;
    int tx = tid & 15, ty = tid >> 4;
    int row0 = blockIdx.x*64, col0 = blockIdx.y*64;
    float acc[4][4] = {};
    for (int k0 = 0; k0 < DD; k0 += 8) {
        #pragma unroll
        for (int i = 0; i < 2; i++) {
            int idx = tid*2 + i;
            int r = idx >> 3, kk = idx & 7;
            As[kk][r] = A[(size_t)(row0+r)*FD + k0 + kk];
        }
        #pragma unroll
        for (int i = 0; i < 2; i++) {
            int idx = tid + i*256;
            int kk = idx >> 6, c = idx & 63;
            int gc = col0 + c;
            Bs[kk][c] = (gc < HH2) ? W[(size_t)(k0+kk)*HH2 + gc] : 0.f;
        }
        __syncthreads();
        #pragma unroll
        for (int kk = 0; kk < 8; kk++) {
            float a[4], b[4];
            #pragma unroll
            for (int i = 0; i < 4; i++) a[i] = As[kk][ty*4+i];
            #pragma unroll
            for (int j = 0; j < 4; j++) b[j] = Bs[kk][tx*4+j];
            #pragma unroll
            for (int i = 0; i < 4; i++)
                #pragma unroll
                for (int j = 0; j < 4; j++)
                    acc[i][j] += a[i]*b[j];
        }
        __syncthreads();
    }
    #pragma unroll
    for (int i = 0; i < 4; i++) {
        int gr = row0 + ty*4 + i;
        #pragma unroll
        for (int j = 0; j < 4; j++) {
            int gc = col0 + tx*4 + j;
            if (gc < HH2)
                C[(size_t)gr*HH2 + gc] = fmaxf(acc[i][j] + bb[gc], 0.f);
        }
    }
}

// ---------------- CLUB layer 2 + loss reduction ------------------------------
__global__ void k_club2(const float* __restrict__ semb, const int* __restrict__ perm,
                        const float* __restrict__ mu_w2, const float* __restrict__ mu_b2,
                        const float* __restrict__ lv_w2, const float* __restrict__ lv_b2,
                        float* __restrict__ mi) {
    const int cj[6] = {1,2,3,2,3,3};
    int b = blockIdx.x, cnt = blockIdx.y;
    __shared__ float hm[HH2];
    __shared__ float hl[HH2];
    __shared__ float red[256];
    int tid = threadIdx.x;
    if (tid < HH2)            hm[tid]     = g_h[((size_t)(cnt*2+0)*BB + b)*HH2 + tid];
    else if (tid < 2*HH2)     hl[tid-HH2] = g_h[((size_t)(cnt*2+1)*BB + b)*HH2 + (tid-HH2)];
    __syncthreads();
    float c = 0.f;
    if (tid < DD) {
        int d = tid;
        float mu = mu_b2[cnt*DD + d];
        float lv = lv_b2[cnt*DD + d];
        const float* wm = mu_w2 + (size_t)cnt*HH2*DD + d;
        const float* wl = lv_w2 + (size_t)cnt*HH2*DD + d;
        #pragma unroll 4
        for (int h = 0; h < HH2; h++) {
            mu += hm[h]*wm[(size_t)h*DD];
            lv += hl[h]*wl[(size_t)h*DD];
        }
        lv = tanhf(lv);
        int j = cj[cnt];
        float yj  = semb[(size_t)b*FD + j*DD + d];
        float yjp = semb[(size_t)perm[b]*FD + j*DD + d];
        float d1 = mu - yj, d2 = mu - yjp;
        c = (d2*d2 - d1*d1) * expf(-lv);
    }
    red[tid] = c; __syncthreads();
    for (int o = 128; o > 0; o >>= 1) {
        if (tid < o) red[tid] += red[tid+o];
        __syncthreads();
    }
    if (tid == 0) atomicAdd(mi, red[0] * (0.5f/BB));
}

// ---------------- launch ------------------------------------------------------
extern "C" void kernel_launch(void* const* d_in, const int* in_sizes, int n_in,
                              void* d_out, int out_size) {
    const int*   sub        = (const int*)  d_in[0];
    const int*   rel        = (const int*)  d_in[1];
    const int*   eidx       = (const int*)  d_in[2];
    const int*   etype      = (const int*)  d_in[3];
    const int*   perm       = (const int*)  d_in[4];
    const float* init_embed = (const float*)d_in[5];
    const float* init_rel   = (const float*)d_in[6];
    const float* pca_w      = (const float*)d_in[7];
    const float* pca_b      = (const float*)d_in[8];
    const float* cw_w       = (const float*)d_in[9];
    const float* w_rel      = (const float*)d_in[10];
    const float* mu_w1      = (const float*)d_in[11];
    const float* mu_b1      = (const float*)d_in[12];
    const float* mu_w2      = (const float*)d_in[13];
    const float* mu_b2      = (const float*)d_in[14];
    const float* lv_w1      = (const float*)d_in[15];
    const float* lv_b1      = (const float*)d_in[16];
    const float* lv_w2      = (const float*)d_in[17];
    const float* lv_b2      = (const float*)d_in[18];
    float* out = (float*)d_out;

    const int* src = eidx;
    const int* dst = eidx + EE;

    float *xA, *xB, *kw, *r1, *H;
    cudaGetSymbolAddress((void**)&xA, g_xA);
    cudaGetSymbolAddress((void**)&xB, g_xB);
    cudaGetSymbolAddress((void**)&kw, g_kw);
    cudaGetSymbolAddress((void**)&r1, g_r1);
    cudaGetSymbolAddress((void**)&H, g_h);

    const int NB = (NN + 255)/256;  // 157

    // 1-3: CSR part 1
    k_zero<<<NB, 256>>>(out + MI_OFF);
    k_hist<<<(EE + 255)/256, 256>>>(dst);
    k_scan1<<<NB, 256>>>();

    // 4: x0 = tanh(init_embed @ pca_w + pca_b) -> xA (head-major)
    {
        dim3 g((NN + 127)/128, (FD + 63)/64);
        k_sgemm3<<<g, 128>>>(init_embed, INITD, pca_w, FD, pca_b, xA, FD,
                             NN, FD, INITD, 1, 1);
    }
    // 5: kw_raw = leaky(x0 @ cw_w) -> xB temp (rows = head-major row order)
    {
        dim3 g((NN*FF + 127)/128, (DD + 63)/64);
        k_sgemm3<<<g, 128>>>(xA, DD, cw_w, DD, nullptr, xB, DD,
                             NN*FF, DD, DD, 2, 0);
    }

    // 6-8: CSR part 2
    k_scan2<<<1, 256>>>(NB);
    k_scan3<<<NB, 256>>>();
    k_fill<<<(EE + 255)/256, 256>>>(src, dst, etype);

    // 9: kw softmax over F (head-major)
    k_kwsm<<<(NN*DD + 255)/256, 256>>>(xB, kw);

    // 10-11: layer 0 (xA -> xB head-major), r = init_rel, 2 head-pair passes
    k_layer2h<<<NN/8, 256>>>(xA, kw, init_rel, xB, 0, 0);
    k_layer2h<<<NN/8, 256>>>(xA, kw, init_rel, xB, 2, 0);

    // 12: r1 = init_rel @ w_rel[0]
    {
        dim3 g((NRELD + 127)/128, (DD + 63)/64);
        k_sgemm3<<<g, 128>>>(init_rel, DD, w_rel, DD, nullptr, r1, DD,
                             NRELD, DD, DD, 0, 0);
    }

    // 13-14: layer 1 (xB -> out x region, interleaved), r = r1
    k_layer2h<<<NN/8, 256>>>(xB, kw, r1, out + X_OFF, 0, 1);
    k_layer2h<<<NN/8, 256>>>(xB, kw, r1, out + X_OFF, 2, 1);

    // 15-16: sub_emb, rel_emb
    k_subemb<<<BB, 256>>>(sub, out + X_OFF, out + SUB_OFF);
    k_relemb<<<BB, 256>>>(rel, init_rel, out + REL_OFF);

    // 17-18: CLUB
    {
        dim3 g(BB/64, (HH2 + 63)/64, 12);
        k_club1<<<g, 256>>>(out + SUB_OFF, mu_w1, mu_b1, lv_w1, lv_b1, H);
    }
    {
        dim3 g(BB, NPAIR);
        k_club2<<<g, 256>>>(out + SUB_OFF, perm, mu_w2, mu_b2, lv_w2, lv_b2,
                            out + MI_OFF);
    }
}

// round 4
// speedup vs baseline: 1.2459x; 1.0150x over previous
#include <cuda_runtime.h>
#include <math.h>

#define NN    40000
#define INITD 100
#define DD    200
#define FF    4
#define EE    800000
#define NRELD 800
#define BB    2048
#define HH2   100
#define NPAIR 6
#define FD    (FF*DD)   // 800

#define SUB_OFF 0
#define REL_OFF ((size_t)BB*FD)
#define X_OFF   ((size_t)2*BB*FD)
#define MI_OFF  ((size_t)2*BB*FD + (size_t)NN*FD)

typedef unsigned long long u64t;

// ---------------- scratch ----------------------------------------------------
__device__ float g_xA[(size_t)NN*FD];   // head-major [F][N][D]
__device__ float g_xB[(size_t)NN*FD];
__device__ float g_kw[(size_t)NN*FD];
__device__ float g_r1[NRELD*DD];
__device__ float g_h[12*BB*HH2];
__device__ float g_o2[12*BB*DD];
__device__ int   g_deg[NN];
__device__ int   g_cur[NN];
__device__ int   g_rowptr[NN+1];
__device__ int   g_csrc[EE];
__device__ int   g_cet[EE];
__device__ int   g_bsums[256];
__device__ int   g_boffs[256];

// ---------------- packed f32x2 helpers ---------------------------------------
__device__ __forceinline__ void ffma2(u64t& d, u64t a, u64t b) {
    asm("fma.rn.f32x2 %0, %1, %2, %0;" : "+l"(d) : "l"(a), "l"(b));
}
__device__ __forceinline__ u64t dup2(float x) {
    u64t r; asm("mov.b64 %0, {%1, %2};" : "=l"(r) : "f"(x), "f"(x)); return r;
}
__device__ __forceinline__ float2 unpack2(u64t v) {
    float lo, hi; asm("mov.b64 {%0, %1}, %2;" : "=f"(lo), "=f"(hi) : "l"(v));
    return make_float2(lo, hi);
}

// ---------------- CSR build ---------------------------------------------------
__global__ void k_zero(float* mi) {
    int i = blockIdx.x*blockDim.x + threadIdx.x;
    if (i < NN) { g_deg[i] = 0; g_cur[i] = 0; }
    if (i == 0) *mi = 0.f;
}
__global__ void k_hist(const int* __restrict__ dst) {
    int e = blockIdx.x*blockDim.x + threadIdx.x;
    if (e < EE) atomicAdd(&g_deg[dst[e]], 1);
}
__global__ void k_scan1() {
    __shared__ int s[256];
    int tid = threadIdx.x;
    int i = blockIdx.x*256 + tid;
    int v = (i < NN) ? g_deg[i] : 0;
    s[tid] = v; __syncthreads();
    for (int off = 1; off < 256; off <<= 1) {
        int t = (tid >= off) ? s[tid-off] : 0;
        __syncthreads(); s[tid] += t; __syncthreads();
    }
    if (i < NN) g_rowptr[i] = s[tid] - v;
    if (tid == 255) g_bsums[blockIdx.x] = s[255];
}
__global__ void k_scan2(int nb) {
    __shared__ int s[256];
    int tid = threadIdx.x;
    int v = (tid < nb) ? g_bsums[tid] : 0;
    s[tid] = v; __syncthreads();
    for (int off = 1; off < 256; off <<= 1) {
        int t = (tid >= off) ? s[tid-off] : 0;
        __syncthreads(); s[tid] += t; __syncthreads();
    }
    if (tid < nb) g_boffs[tid] = s[tid] - v;
}
__global__ void k_scan3() {
    int tid = threadIdx.x;
    int i = blockIdx.x*256 + tid;
    if (i < NN) g_rowptr[i] += g_boffs[blockIdx.x];
    if (i == 0) g_rowptr[NN] = EE;
}
__global__ void k_fill(const int* __restrict__ src, const int* __restrict__ dst,
                       const int* __restrict__ et) {
    int e = blockIdx.x*blockDim.x + threadIdx.x;
    if (e >= EE) return;
    int d = dst[e];
    int pos = g_rowptr[d] + atomicAdd(&g_cur[d], 1);
    g_csrc[pos] = src[e];
    g_cet[pos]  = et[e];
}

// ---------------- SGEMM v4: double-buffered 128x64, 8x8 micro, f32x2 --------
// act: 0=none 1=tanh 2=leaky(0.2) 3=relu
// hm:  head-major store: col gc -> (f=gc/DD, d=gc%DD) at f*NN*DD + row*DD + d
__global__ __launch_bounds__(128, 4)
void k_sgemm4(const float* __restrict__ A, int lda,
              const float* __restrict__ B, int ldb,
              const float* __restrict__ bias,
              float* __restrict__ C, int ldc,
              int M, int N, int K, int act, int hm) {
    __shared__ __align__(16) float As[2][16][128];
    __shared__ __align__(16) float Bs[2][16][64];
    int tid = threadIdx.x;
    int tx = tid & 7, ty = tid >> 3;
    int row0 = blockIdx.x*128, col0 = blockIdx.y*64;
    int bk = tid >> 3, bc = (tid & 7) * 8;

    u64t acc[4][8];
    #pragma unroll
    for (int i = 0; i < 4; i++)
        #pragma unroll
        for (int j = 0; j < 8; j++) acc[i][j] = 0ull;

    float pa[16], pb[8];
    int nkt = (K + 15) >> 4;

    // prefetch tile 0
    {
        int k0 = 0;
        if (k0 + 16 <= K && row0 + 128 <= M) {
            const float* ap = A + (size_t)(row0 + tid)*lda + k0;
            float4 v0=*(const float4*)ap, v1=*(const float4*)(ap+4);
            float4 v2=*(const float4*)(ap+8), v3=*(const float4*)(ap+12);
            pa[0]=v0.x;pa[1]=v0.y;pa[2]=v0.z;pa[3]=v0.w;
            pa[4]=v1.x;pa[5]=v1.y;pa[6]=v1.z;pa[7]=v1.w;
            pa[8]=v2.x;pa[9]=v2.y;pa[10]=v2.z;pa[11]=v2.w;
            pa[12]=v3.x;pa[13]=v3.y;pa[14]=v3.z;pa[15]=v3.w;
        } else {
            int gr = row0 + tid;
            #pragma unroll
            for (int c = 0; c < 16; c++)
                pa[c] = (gr < M && k0 + c < K) ? A[(size_t)gr*lda + k0 + c] : 0.f;
        }
        if (k0 + bk < K && col0 + 64 <= N) {
            const float* bp = B + (size_t)(k0 + bk)*ldb + col0 + bc;
            float4 v0=*(const float4*)bp, v1=*(const float4*)(bp+4);
            pb[0]=v0.x;pb[1]=v0.y;pb[2]=v0.z;pb[3]=v0.w;
            pb[4]=v1.x;pb[5]=v1.y;pb[6]=v1.z;pb[7]=v1.w;
        } else {
            #pragma unroll
            for (int c = 0; c < 8; c++) {
                int gc = col0 + bc + c;
                pb[c] = (k0 + bk < K && gc < N) ? B[(size_t)(k0+bk)*ldb + gc] : 0.f;
            }
        }
        #pragma unroll
        for (int c = 0; c < 16; c++) As[0][c][tid] = pa[c];
        *(float4*)&Bs[0][bk][bc]   = make_float4(pb[0],pb[1],pb[2],pb[3]);
        *(float4*)&Bs[0][bk][bc+4] = make_float4(pb[4],pb[5],pb[6],pb[7]);
    }
    __syncthreads();

    for (int kt = 0; kt < nkt; kt++) {
        int cur = kt & 1;
        if (kt + 1 < nkt) {
            int k0 = (kt + 1) * 16;
            if (k0 + 16 <= K && row0 + 128 <= M) {
                const float* ap = A + (size_t)(row0 + tid)*lda + k0;
                float4 v0=*(const float4*)ap, v1=*(const float4*)(ap+4);
                float4 v2=*(const float4*)(ap+8), v3=*(const float4*)(ap+12);
                pa[0]=v0.x;pa[1]=v0.y;pa[2]=v0.z;pa[3]=v0.w;
                pa[4]=v1.x;pa[5]=v1.y;pa[6]=v1.z;pa[7]=v1.w;
                pa[8]=v2.x;pa[9]=v2.y;pa[10]=v2.z;pa[11]=v2.w;
                pa[12]=v3.x;pa[13]=v3.y;pa[14]=v3.z;pa[15]=v3.w;
            } else {
                int gr = row0 + tid;
                #pragma unroll
                for (int c = 0; c < 16; c++)
                    pa[c] = (gr < M && k0 + c < K) ? A[(size_t)gr*lda + k0 + c] : 0.f;
            }
            if (k0 + bk < K && col0 + 64 <= N) {
                const float* bp = B + (size_t)(k0 + bk)*ldb + col0 + bc;
                float4 v0=*(const float4*)bp, v1=*(const float4*)(bp+4);
                pb[0]=v0.x;pb[1]=v0.y;pb[2]=v0.z;pb[3]=v0.w;
                pb[4]=v1.x;pb[5]=v1.y;pb[6]=v1.z;pb[7]=v1.w;
            } else {
                #pragma unroll
                for (int c = 0; c < 8; c++) {
                    int gc = col0 + bc + c;
                    pb[c] = (k0 + bk < K && gc < N) ? B[(size_t)(k0+bk)*ldb + gc] : 0.f;
                }
            }
        }
        #pragma unroll
        for (int kk = 0; kk < 16; kk++) {
            const ulonglong2* ap2 = (const ulonglong2*)&As[cur][kk][ty*8];
            ulonglong2 aA = ap2[0];
            ulonglong2 aB = ap2[1];
            float4 bv0 = *(const float4*)&Bs[cur][kk][tx*8];
            float4 bv1 = *(const float4*)&Bs[cur][kk][tx*8+4];
            u64t b[8];
            b[0]=dup2(bv0.x); b[1]=dup2(bv0.y); b[2]=dup2(bv0.z); b[3]=dup2(bv0.w);
            b[4]=dup2(bv1.x); b[5]=dup2(bv1.y); b[6]=dup2(bv1.z); b[7]=dup2(bv1.w);
            #pragma unroll
            for (int j = 0; j < 8; j++) {
                ffma2(acc[0][j], aA.x, b[j]);
                ffma2(acc[1][j], aA.y, b[j]);
                ffma2(acc[2][j], aB.x, b[j]);
                ffma2(acc[3][j], aB.y, b[j]);
            }
        }
        if (kt + 1 < nkt) {
            int nxt = cur ^ 1;
            #pragma unroll
            for (int c = 0; c < 16; c++) As[nxt][c][tid] = pa[c];
            *(float4*)&Bs[nxt][bk][bc]   = make_float4(pb[0],pb[1],pb[2],pb[3]);
            *(float4*)&Bs[nxt][bk][bc+4] = make_float4(pb[4],pb[5],pb[6],pb[7]);
        }
        __syncthreads();
    }

    #pragma unroll
    for (int i = 0; i < 4; i++) {
        int r0 = row0 + ty*8 + i*2;
        #pragma unroll
        for (int j = 0; j < 8; j++) {
            int gc = col0 + tx*8 + j;
            if (gc >= N) continue;
            float2 p = unpack2(acc[i][j]);
            float bv = bias ? bias[gc] : 0.f;
            float v0 = p.x + bv, v1 = p.y + bv;
            if (act == 1) { v0 = tanhf(v0); v1 = tanhf(v1); }
            else if (act == 2) { v0 = (v0 > 0.f) ? v0 : 0.2f*v0; v1 = (v1 > 0.f) ? v1 : 0.2f*v1; }
            else if (act == 3) { v0 = fmaxf(v0, 0.f); v1 = fmaxf(v1, 0.f); }
            if (hm) {
                int f = gc / DD, d = gc - f*DD;
                size_t base = (size_t)f*NN*DD + d;
                if (r0     < M) C[base + (size_t)r0    *DD] = v0;
                if (r0 + 1 < M) C[base + (size_t)(r0+1)*DD] = v1;
            } else {
                if (r0     < M) C[(size_t)r0    *ldc + gc] = v0;
                if (r0 + 1 < M) C[(size_t)(r0+1)*ldc + gc] = v1;
            }
        }
    }
}

// ---------------- kw softmax over F axis (head-major) ------------------------
__global__ void k_kwsm(const float* __restrict__ raw, float* __restrict__ kw) {
    int i = blockIdx.x*blockDim.x + threadIdx.x;
    if (i >= NN*DD) return;
    const float* p = raw + i;
    const size_t S = (size_t)NN*DD;
    float a0 = p[0], a1 = p[S], a2 = p[2*S], a3 = p[3*S];
    float m = fmaxf(fmaxf(a0, a1), fmaxf(a2, a3));
    float e0 = __expf(a0-m), e1 = __expf(a1-m), e2 = __expf(a2-m), e3 = __expf(a3-m);
    float inv = 1.f/(e0+e1+e2+e3);
    float* q = kw + i;
    q[0] = e0*inv; q[S] = e1*inv; q[2*S] = e2*inv; q[3*S] = e3*inv;
}

// ---------------- attention layer: warp/node, 2 heads, float4 loads ---------
// lane < 25 owns 8 consecutive d's (lane*8 .. lane*8+7)
__global__ void k_layer2h(const float* __restrict__ x, const float* __restrict__ kw,
                          const float* __restrict__ r, float* __restrict__ xout,
                          int hb, int ilv) {
    int warp = threadIdx.x >> 5, lane = threadIdx.x & 31;
    int v = blockIdx.x*8 + warp;
    bool on = lane < 25;
    int off = lane * 8;
    const float* X0 = x + (size_t)hb    *NN*DD;
    const float* X1 = x + (size_t)(hb+1)*NN*DD;

    float xd0[8], xd1[8], acc0[8], acc1[8];
    #pragma unroll
    for (int j = 0; j < 8; j++) { xd0[j]=0.f; xd1[j]=0.f; acc0[j]=0.f; acc1[j]=0.f; }
    if (on) {
        const float4* p0 = (const float4*)(X0 + (size_t)v*DD + off);
        const float4* p1 = (const float4*)(X1 + (size_t)v*DD + off);
        float4 a = p0[0], b = p0[1];
        xd0[0]=a.x;xd0[1]=a.y;xd0[2]=a.z;xd0[3]=a.w; xd0[4]=b.x;xd0[5]=b.y;xd0[6]=b.z;xd0[7]=b.w;
        a = p1[0]; b = p1[1];
        xd1[0]=a.x;xd1[1]=a.y;xd1[2]=a.z;xd1[3]=a.w; xd1[4]=b.x;xd1[5]=b.y;xd1[6]=b.z;xd1[7]=b.w;
    }
    float rm0 = -INFINITY, rs0 = 0.f, rm1 = -INFINITY, rs1 = 0.f;

    int e0 = g_rowptr[v], e1 = g_rowptr[v+1];
    for (int eb = e0; eb < e1; eb += 2) {
        int m = min(2, e1 - eb);
        float xs0[2][8], xs1[2][8], rr[2][8];
        float p0v[2], p1v[2];
        #pragma unroll
        for (int c = 0; c < 2; c++) {
            p0v[c] = 0.f; p1v[c] = 0.f;
            if (c >= m) continue;
            int s  = g_csrc[eb+c];
            int et = g_cet[eb+c];
            if (on) {
                const float4* xp0 = (const float4*)(X0 + (size_t)s*DD + off);
                const float4* xp1 = (const float4*)(X1 + (size_t)s*DD + off);
                const float4* rp  = (const float4*)(r  + (size_t)et*DD + off);
                float4 a, b;
                a = xp0[0]; b = xp0[1];
                xs0[c][0]=a.x;xs0[c][1]=a.y;xs0[c][2]=a.z;xs0[c][3]=a.w;
                xs0[c][4]=b.x;xs0[c][5]=b.y;xs0[c][6]=b.z;xs0[c][7]=b.w;
                a = xp1[0]; b = xp1[1];
                xs1[c][0]=a.x;xs1[c][1]=a.y;xs1[c][2]=a.z;xs1[c][3]=a.w;
                xs1[c][4]=b.x;xs1[c][5]=b.y;xs1[c][6]=b.z;xs1[c][7]=b.w;
                a = rp[0]; b = rp[1];
                rr[c][0]=a.x;rr[c][1]=a.y;rr[c][2]=a.z;rr[c][3]=a.w;
                rr[c][4]=b.x;rr[c][5]=b.y;rr[c][6]=b.z;rr[c][7]=b.w;
                float s0 = 0.f, s1 = 0.f;
                #pragma unroll
                for (int j = 0; j < 8; j++) {
                    s0 += xs0[c][j]*rr[c][j]*xd0[j];
                    s1 += xs1[c][j]*rr[c][j]*xd1[j];
                }
                p0v[c] = s0; p1v[c] = s1;
            } else {
                #pragma unroll
                for (int j = 0; j < 8; j++) { xs0[c][j]=0.f; xs1[c][j]=0.f; rr[c][j]=0.f; }
            }
        }
        #pragma unroll
        for (int o = 16; o > 0; o >>= 1) {
            p0v[0] += __shfl_xor_sync(0xffffffffu, p0v[0], o);
            p0v[1] += __shfl_xor_sync(0xffffffffu, p0v[1], o);
            p1v[0] += __shfl_xor_sync(0xffffffffu, p1v[0], o);
            p1v[1] += __shfl_xor_sync(0xffffffffu, p1v[1], o);
        }
        #pragma unroll
        for (int c = 0; c < 2; c++) {
            if (c >= m) break;
            {
                float dot = p0v[c];
                float l = (dot > 0.f) ? dot : 0.2f*dot;
                float nm = fmaxf(rm0, l);
                float sc = (rm0 == -INFINITY) ? 0.f : __expf(rm0 - nm);
                float w = __expf(l - nm);
                rm0 = nm; rs0 = rs0*sc + w;
                #pragma unroll
                for (int j = 0; j < 8; j++)
                    acc0[j] = acc0[j]*sc + w*(xs0[c][j]*rr[c][j]);
            }
            {
                float dot = p1v[c];
                float l = (dot > 0.f) ? dot : 0.2f*dot;
                float nm = fmaxf(rm1, l);
                float sc = (rm1 == -INFINITY) ? 0.f : __expf(rm1 - nm);
                float w = __expf(l - nm);
                rm1 = nm; rs1 = rs1*sc + w;
                #pragma unroll
                for (int j = 0; j < 8; j++)
                    acc1[j] = acc1[j]*sc + w*(xs1[c][j]*rr[c][j]);
            }
        }
    }
    if (!on) return;
    float inv0 = 1.f/(rs0 + 1e-16f);
    float inv1 = 1.f/(rs1 + 1e-16f);
    const float* kw0 = kw + ((size_t)hb    *NN + v)*DD + off;
    const float* kw1 = kw + ((size_t)(hb+1)*NN + v)*DD + off;
    float o0[8], o1[8];
    #pragma unroll
    for (int j = 0; j < 8; j++) {
        o0[j] = tanhf(acc0[j]*inv0) * kw0[j];
        o1[j] = tanhf(acc1[j]*inv1) * kw1[j];
    }
    float* w0; float* w1;
    if (ilv) {
        w0 = xout + (size_t)v*FD + (size_t)hb    *DD + off;
        w1 = xout + (size_t)v*FD + (size_t)(hb+1)*DD + off;
    } else {
        w0 = xout + ((size_t)hb    *NN + v)*DD + off;
        w1 = xout + ((size_t)(hb+1)*NN + v)*DD + off;
    }
    ((float4*)w0)[0] = make_float4(o0[0],o0[1],o0[2],o0[3]);
    ((float4*)w0)[1] = make_float4(o0[4],o0[5],o0[6],o0[7]);
    ((float4*)w1)[0] = make_float4(o1[0],o1[1],o1[2],o1[3]);
    ((float4*)w1)[1] = make_float4(o1[4],o1[5],o1[6],o1[7]);
}

// ---------------- output gathers ----------------------------------------------
__global__ void k_subemb(const int* __restrict__ sub, const float* __restrict__ x,
                         float* __restrict__ o) {
    int b = blockIdx.x;
    int row = sub[b];
    for (int idx = threadIdx.x; idx < FD; idx += blockDim.x)
        o[(size_t)b*FD + idx] = x[(size_t)row*FD + idx];
}
__global__ void k_relemb(const int* __restrict__ rel, const float* __restrict__ ir,
                         float* __restrict__ o) {
    int b = blockIdx.x;
    int row = rel[b];
    for (int idx = threadIdx.x; idx < FD; idx += blockDim.x) {
        int d = idx % DD;
        o[(size_t)b*FD + idx] = ir[(size_t)row*DD + d];
    }
}

// ---------------- CLUB layer 1 (12 batched GEMMs, relu) ----------------------
__global__ void k_club1(const float* __restrict__ semb,
                        const float* __restrict__ mu_w1, const float* __restrict__ mu_b1,
                        const float* __restrict__ lv_w1, const float* __restrict__ lv_b1,
                        float* __restrict__ H) {
    const int ci[6] = {0,0,0,1,1,2};
    int z = blockIdx.z, cnt = z >> 1, net = z & 1;
    const float* A  = semb + ci[cnt]*DD;  // lda = FD
    const float* W  = (net ? lv_w1 : mu_w1) + (size_t)cnt*DD*HH2;
    const float* bb = (net ? lv_b1 : mu_b1) + cnt*HH2;
    float* C = H + (size_t)z*BB*HH2;

    __shared__ float As[8][64];
    __shared__ float Bs[8][65];
    int tid = threadIdx.x;
    int tx = tid & 15, ty = tid >> 4;
    int row0 = blockIdx.x*64, col0 = blockIdx.y*64;
    float acc[4][4] = {};
    for (int k0 = 0; k0 < DD; k0 += 8) {
        #pragma unroll
        for (int i = 0; i < 2; i++) {
            int idx = tid*2 + i;
            int rI = idx >> 3, kk = idx & 7;
            As[kk][rI] = A[(size_t)(row0+rI)*FD + k0 + kk];
        }
        #pragma unroll
        for (int i = 0; i < 2; i++) {
            int idx = tid + i*256;
            int kk = idx >> 6, c = idx & 63;
            int gc = col0 + c;
            Bs[kk][c] = (gc < HH2) ? W[(size_t)(k0+kk)*HH2 + gc] : 0.f;
        }
        __syncthreads();
        #pragma unroll
        for (int kk = 0; kk < 8; kk++) {
            float a[4], b[4];
            #pragma unroll
            for (int i = 0; i < 4; i++) a[i] = As[kk][ty*4+i];
            #pragma unroll
            for (int j = 0; j < 4; j++) b[j] = Bs[kk][tx*4+j];
            #pragma unroll
            for (int i = 0; i < 4; i++)
                #pragma unroll
                for (int j = 0; j < 4; j++)
                    acc[i][j] += a[i]*b[j];
        }
        __syncthreads();
    }
    #pragma unroll
    for (int i = 0; i < 4; i++) {
        int gr = row0 + ty*4 + i;
        #pragma unroll
        for (int j = 0; j < 4; j++) {
            int gc = col0 + tx*4 + j;
            if (gc < HH2)
                C[(size_t)gr*HH2 + gc] = fmaxf(acc[i][j] + bb[gc], 0.f);
        }
    }
}

// ---------------- CLUB layer 2 as batched GEMM (z = pair*2 + net) -----------
// C[z] (2048x200) = g_h[z] (2048x100) @ w2[cnt] (100x200) + b2; net1 -> tanh
__global__ __launch_bounds__(128, 4)
void k_club2g(const float* __restrict__ mu_w2, const float* __restrict__ mu_b2,
              const float* __restrict__ lv_w2, const float* __restrict__ lv_b2) {
    __shared__ __align__(16) float As[2][16][128];
    __shared__ __align__(16) float Bs[2][16][64];
    int z = blockIdx.z, cnt = z >> 1, net = z & 1;
    const float* A  = g_h + (size_t)z*BB*HH2;
    const float* W  = (net ? lv_w2 : mu_w2) + (size_t)cnt*HH2*DD;
    const float* bb = (net ? lv_b2 : mu_b2) + cnt*DD;
    float* C = g_o2 + (size_t)z*BB*DD;
    const int M = BB, N = DD, K = HH2;
    int tid = threadIdx.x;
    int tx = tid & 7, ty = tid >> 3;
    int row0 = blockIdx.x*128, col0 = blockIdx.y*64;
    int bk = tid >> 3, bc = (tid & 7) * 8;

    u64t acc[4][8];
    #pragma unroll
    for (int i = 0; i < 4; i++)
        #pragma unroll
        for (int j = 0; j < 8; j++) acc[i][j] = 0ull;

    float pa[16], pb[8];
    int nkt = (K + 15) >> 4;
    #pragma unroll 1
    for (int kt = -1; kt + 1 < nkt + 1; kt++) {
        if (kt + 1 < nkt) {
            int k0 = (kt + 1) * 16;
            int gr = row0 + tid;
            #pragma unroll
            for (int c = 0; c < 16; c++)
                pa[c] = (k0 + c < K) ? A[(size_t)gr*HH2 + k0 + c] : 0.f;
            #pragma unroll
            for (int c = 0; c < 8; c++) {
                int gc = col0 + bc + c;
                pb[c] = (k0 + bk < K && gc < N) ? W[(size_t)(k0+bk)*DD + gc] : 0.f;
            }
        }
        if (kt >= 0) {
            int cur = kt & 1;
            #pragma unroll
            for (int kk = 0; kk < 16; kk++) {
                const ulonglong2* ap2 = (const ulonglong2*)&As[cur][kk][ty*8];
                ulonglong2 aA = ap2[0];
                ulonglong2 aB = ap2[1];
                float4 bv0 = *(const float4*)&Bs[cur][kk][tx*8];
                float4 bv1 = *(const float4*)&Bs[cur][kk][tx*8+4];
                u64t b[8];
                b[0]=dup2(bv0.x); b[1]=dup2(bv0.y); b[2]=dup2(bv0.z); b[3]=dup2(bv0.w);
                b[4]=dup2(bv1.x); b[5]=dup2(bv1.y); b[6]=dup2(bv1.z); b[7]=dup2(bv1.w);
                #pragma unroll
                for (int j = 0; j < 8; j++) {
                    ffma2(acc[0][j], aA.x, b[j]);
                    ffma2(acc[1][j], aA.y, b[j]);
                    ffma2(acc[2][j], aB.x, b[j]);
                    ffma2(acc[3][j], aB.y, b[j]);
                }
            }
        }
        if (kt + 1 < nkt) {
            int nxt = (kt + 1) & 1;
            #pragma unroll
            for (int c = 0; c < 16; c++) As[nxt][c][tid] = pa[c];
            *(float4*)&Bs[nxt][bk][bc]   = make_float4(pb[0],pb[1],pb[2],pb[3]);
            *(float4*)&Bs[nxt][bk][bc+4] = make_float4(pb[4],pb[5],pb[6],pb[7]);
        }
        __syncthreads();
    }
    #pragma unroll
    for (int i = 0; i < 4; i++) {
        int r0 = row0 + ty*8 + i*2;
        #pragma unroll
        for (int j = 0; j < 8; j++) {
            int gc = col0 + tx*8 + j;
            if (gc >= N) continue;
            float2 p = unpack2(acc[i][j]);
            float bv = bb[gc];
            float v0 = p.x + bv, v1 = p.y + bv;
            if (net) { v0 = tanhf(v0); v1 = tanhf(v1); }
            C[(size_t)r0    *DD + gc] = v0;
            C[(size_t)(r0+1)*DD + gc] = v1;
        }
    }
}

// ---------------- loss reduction ----------------------------------------------
__global__ void k_loss(const float* __restrict__ semb, const int* __restrict__ perm,
                       float* __restrict__ mi) {
    const int cj[6] = {1,2,3,2,3,3};
    int b = blockIdx.x, cnt = blockIdx.y;
    __shared__ float red[256];
    int tid = threadIdx.x;
    float c = 0.f;
    if (tid < DD) {
        float mu = g_o2[((size_t)(cnt*2+0)*BB + b)*DD + tid];
        float lv = g_o2[((size_t)(cnt*2+1)*BB + b)*DD + tid];
        int j = cj[cnt];
        float yj  = semb[(size_t)b*FD + j*DD + tid];
        float yjp = semb[(size_t)perm[b]*FD + j*DD + tid];
        float d1 = mu - yj, d2 = mu - yjp;
        c = (d2*d2 - d1*d1) * expf(-lv);
    }
    red[tid] = c; __syncthreads();
    for (int o = 128; o > 0; o >>= 1) {
        if (tid < o) red[tid] += red[tid+o];
        __syncthreads();
    }
    if (tid == 0) atomicAdd(mi, red[0] * (0.5f/BB));
}

// ---------------- launch --------------------------------------------------------
extern "C" void kernel_launch(void* const* d_in, const int* in_sizes, int n_in,
                              void* d_out, int out_size) {
    const int*   sub        = (const int*)  d_in[0];
    const int*   rel        = (const int*)  d_in[1];
    const int*   eidx       = (const int*)  d_in[2];
    const int*   etype      = (const int*)  d_in[3];
    const int*   perm       = (const int*)  d_in[4];
    const float* init_embed = (const float*)d_in[5];
    const float* init_rel   = (const float*)d_in[6];
    const float* pca_w      = (const float*)d_in[7];
    const float* pca_b      = (const float*)d_in[8];
    const float* cw_w       = (const float*)d_in[9];
    const float* w_rel      = (const float*)d_in[10];
    const float* mu_w1      = (const float*)d_in[11];
    const float* mu_b1      = (const float*)d_in[12];
    const float* mu_w2      = (const float*)d_in[13];
    const float* mu_b2      = (const float*)d_in[14];
    const float* lv_w1      = (const float*)d_in[15];
    const float* lv_b1      = (const float*)d_in[16];
    const float* lv_w2      = (const float*)d_in[17];
    const float* lv_b2      = (const float*)d_in[18];
    float* out = (float*)d_out;

    const int* src = eidx;
    const int* dst = eidx + EE;

    float *xA, *xB, *kw, *r1, *H;
    cudaGetSymbolAddress((void**)&xA, g_xA);
    cudaGetSymbolAddress((void**)&xB, g_xB);
    cudaGetSymbolAddress((void**)&kw, g_kw);
    cudaGetSymbolAddress((void**)&r1, g_r1);
    cudaGetSymbolAddress((void**)&H, g_h);

    const int NB = (NN + 255)/256;

    // 1-3
    k_zero<<<NB, 256>>>(out + MI_OFF);
    k_hist<<<(EE + 255)/256, 256>>>(dst);
    k_scan1<<<NB, 256>>>();

    // 4: x0 GEMM (captured by ncu)
    {
        dim3 g((NN + 127)/128, (FD + 63)/64);
        k_sgemm4<<<g, 128>>>(init_embed, INITD, pca_w, FD, pca_b, xA, FD,
                             NN, FD, INITD, 1, 1);
    }
    // 5: kw GEMM
    {
        dim3 g((NN*FF + 127)/128, (DD + 63)/64);
        k_sgemm4<<<g, 128>>>(xA, DD, cw_w, DD, nullptr, xB, DD,
                             NN*FF, DD, DD, 2, 0);
    }

    // 6-8: CSR part 2
    k_scan2<<<1, 256>>>(NB);
    k_scan3<<<NB, 256>>>();
    k_fill<<<(EE + 255)/256, 256>>>(src, dst, etype);

    // 9: kw softmax
    k_kwsm<<<(NN*DD + 255)/256, 256>>>(xB, kw);

    // 10-11: layer 0
    k_layer2h<<<NN/8, 256>>>(xA, kw, init_rel, xB, 0, 0);
    k_layer2h<<<NN/8, 256>>>(xA, kw, init_rel, xB, 2, 0);

    // 12: r1 = init_rel @ w_rel[0]
    {
        dim3 g((NRELD + 127)/128, (DD + 63)/64);
        k_sgemm4<<<g, 128>>>(init_rel, DD, w_rel, DD, nullptr, r1, DD,
                             NRELD, DD, DD, 0, 0);
    }

    // 13-14: layer 1 -> output x (interleaved)
    k_layer2h<<<NN/8, 256>>>(xB, kw, r1, out + X_OFF, 0, 1);
    k_layer2h<<<NN/8, 256>>>(xB, kw, r1, out + X_OFF, 2, 1);

    // 15-16
    k_subemb<<<BB, 256>>>(sub, out + X_OFF, out + SUB_OFF);
    k_relemb<<<BB, 256>>>(rel, init_rel, out + REL_OFF);

    // 17: CLUB layer 1
    {
        dim3 g(BB/64, (HH2 + 63)/64, 12);
        k_club1<<<g, 256>>>(out + SUB_OFF, mu_w1, mu_b1, lv_w1, lv_b1, H);
    }
    // 18: CLUB layer 2 (batched GEMM)
    {
        dim3 g(BB/128, (DD + 63)/64, 12);
        k_club2g<<<g, 128>>>(mu_w2, mu_b2, lv_w2, lv_b2);
    }
    // 19: loss
    {
        dim3 g(BB, NPAIR);
        k_loss<<<g, 256>>>(out + SUB_OFF, perm, out + MI_OFF);
    }
}

// round 5
// speedup vs baseline: 1.2734x; 1.0220x over previous
#include <cuda_runtime.h>
#include <math.h>

#define NN    40000
#define INITD 100
#define DD    200
#define FF    4
#define EE    800000
#define NRELD 800
#define BB    2048
#define HH2   100
#define NPAIR 6
#define FD    (FF*DD)   // 800

#define SUB_OFF 0
#define REL_OFF ((size_t)BB*FD)
#define X_OFF   ((size_t)2*BB*FD)
#define MI_OFF  ((size_t)2*BB*FD + (size_t)NN*FD)

typedef unsigned long long u64t;

// ---------------- scratch ----------------------------------------------------
__device__ float g_xA[(size_t)NN*FD];   // head-major [F][N][D]
__device__ float g_xB[(size_t)NN*FD];
__device__ float g_kw[(size_t)NN*FD];
__device__ float g_r1[NRELD*DD];
__device__ float g_h[12*BB*HH2];
__device__ float g_o2[12*BB*DD];
__device__ int   g_deg[NN];
__device__ int   g_cur[NN];
__device__ int   g_rowptr[NN+1];
__device__ int   g_csrc[EE];
__device__ int   g_cet[EE];
__device__ int   g_bsums[256];
__device__ int   g_boffs[256];

// ---------------- packed f32x2 helpers ---------------------------------------
__device__ __forceinline__ void ffma2(u64t& d, u64t a, u64t b) {
    asm("fma.rn.f32x2 %0, %1, %2, %0;" : "+l"(d) : "l"(a), "l"(b));
}
__device__ __forceinline__ u64t dup2(float x) {
    u64t r; asm("mov.b64 %0, {%1, %2};" : "=l"(r) : "f"(x), "f"(x)); return r;
}
__device__ __forceinline__ float2 unpack2(u64t v) {
    float lo, hi; asm("mov.b64 {%0, %1}, %2;" : "=f"(lo), "=f"(hi) : "l"(v));
    return make_float2(lo, hi);
}

// ---------------- CSR build ---------------------------------------------------
__global__ void k_zero(float* mi) {
    int i = blockIdx.x*blockDim.x + threadIdx.x;
    if (i < NN) { g_deg[i] = 0; g_cur[i] = 0; }
    if (i == 0) *mi = 0.f;
}
__global__ void k_hist(const int* __restrict__ dst) {
    int e = blockIdx.x*blockDim.x + threadIdx.x;
    if (e < EE) atomicAdd(&g_deg[dst[e]], 1);
}
__global__ void k_scan1() {
    __shared__ int s[256];
    int tid = threadIdx.x;
    int i = blockIdx.x*256 + tid;
    int v = (i < NN) ? g_deg[i] : 0;
    s[tid] = v; __syncthreads();
    for (int off = 1; off < 256; off <<= 1) {
        int t = (tid >= off) ? s[tid-off] : 0;
        __syncthreads(); s[tid] += t; __syncthreads();
    }
    if (i < NN) g_rowptr[i] = s[tid] - v;
    if (tid == 255) g_bsums[blockIdx.x] = s[255];
}
__global__ void k_scan2(int nb) {
    __shared__ int s[256];
    int tid = threadIdx.x;
    int v = (tid < nb) ? g_bsums[tid] : 0;
    s[tid] = v; __syncthreads();
    for (int off = 1; off < 256; off <<= 1) {
        int t = (tid >= off) ? s[tid-off] : 0;
        __syncthreads(); s[tid] += t; __syncthreads();
    }
    if (tid < nb) g_boffs[tid] = s[tid] - v;
}
__global__ void k_scan3() {
    int tid = threadIdx.x;
    int i = blockIdx.x*256 + tid;
    if (i < NN) g_rowptr[i] += g_boffs[blockIdx.x];
    if (i == 0) g_rowptr[NN] = EE;
}
__global__ void k_fill(const int* __restrict__ src, const int* __restrict__ dst,
                       const int* __restrict__ et) {
    int e = blockIdx.x*blockDim.x + threadIdx.x;
    if (e >= EE) return;
    int d = dst[e];
    int pos = g_rowptr[d] + atomicAdd(&g_cur[d], 1);
    g_csrc[pos] = src[e];
    g_cet[pos]  = et[e];
}

// ---------------- SGEMM v4: double-buffered 128x64, 8x8 micro, f32x2 --------
__global__ __launch_bounds__(128, 4)
void k_sgemm4(const float* __restrict__ A, int lda,
              const float* __restrict__ B, int ldb,
              const float* __restrict__ bias,
              float* __restrict__ C, int ldc,
              int M, int N, int K, int act, int hm) {
    __shared__ __align__(16) float As[2][16][128];
    __shared__ __align__(16) float Bs[2][16][64];
    int tid = threadIdx.x;
    int tx = tid & 7, ty = tid >> 3;
    int row0 = blockIdx.x*128, col0 = blockIdx.y*64;
    int bk = tid >> 3, bc = (tid & 7) * 8;

    u64t acc[4][8];
    #pragma unroll
    for (int i = 0; i < 4; i++)
        #pragma unroll
        for (int j = 0; j < 8; j++) acc[i][j] = 0ull;

    float pa[16], pb[8];
    int nkt = (K + 15) >> 4;

    {
        int k0 = 0;
        if (k0 + 16 <= K && row0 + 128 <= M) {
            const float* ap = A + (size_t)(row0 + tid)*lda + k0;
            float4 v0=*(const float4*)ap, v1=*(const float4*)(ap+4);
            float4 v2=*(const float4*)(ap+8), v3=*(const float4*)(ap+12);
            pa[0]=v0.x;pa[1]=v0.y;pa[2]=v0.z;pa[3]=v0.w;
            pa[4]=v1.x;pa[5]=v1.y;pa[6]=v1.z;pa[7]=v1.w;
            pa[8]=v2.x;pa[9]=v2.y;pa[10]=v2.z;pa[11]=v2.w;
            pa[12]=v3.x;pa[13]=v3.y;pa[14]=v3.z;pa[15]=v3.w;
        } else {
            int gr = row0 + tid;
            #pragma unroll
            for (int c = 0; c < 16; c++)
                pa[c] = (gr < M && k0 + c < K) ? A[(size_t)gr*lda + k0 + c] : 0.f;
        }
        if (k0 + bk < K && col0 + 64 <= N) {
            const float* bp = B + (size_t)(k0 + bk)*ldb + col0 + bc;
            float4 v0=*(const float4*)bp, v1=*(const float4*)(bp+4);
            pb[0]=v0.x;pb[1]=v0.y;pb[2]=v0.z;pb[3]=v0.w;
            pb[4]=v1.x;pb[5]=v1.y;pb[6]=v1.z;pb[7]=v1.w;
        } else {
            #pragma unroll
            for (int c = 0; c < 8; c++) {
                int gc = col0 + bc + c;
                pb[c] = (k0 + bk < K && gc < N) ? B[(size_t)(k0+bk)*ldb + gc] : 0.f;
            }
        }
        #pragma unroll
        for (int c = 0; c < 16; c++) As[0][c][tid] = pa[c];
        *(float4*)&Bs[0][bk][bc]   = make_float4(pb[0],pb[1],pb[2],pb[3]);
        *(float4*)&Bs[0][bk][bc+4] = make_float4(pb[4],pb[5],pb[6],pb[7]);
    }
    __syncthreads();

    for (int kt = 0; kt < nkt; kt++) {
        int cur = kt & 1;
        if (kt + 1 < nkt) {
            int k0 = (kt + 1) * 16;
            if (k0 + 16 <= K && row0 + 128 <= M) {
                const float* ap = A + (size_t)(row0 + tid)*lda + k0;
                float4 v0=*(const float4*)ap, v1=*(const float4*)(ap+4);
                float4 v2=*(const float4*)(ap+8), v3=*(const float4*)(ap+12);
                pa[0]=v0.x;pa[1]=v0.y;pa[2]=v0.z;pa[3]=v0.w;
                pa[4]=v1.x;pa[5]=v1.y;pa[6]=v1.z;pa[7]=v1.w;
                pa[8]=v2.x;pa[9]=v2.y;pa[10]=v2.z;pa[11]=v2.w;
                pa[12]=v3.x;pa[13]=v3.y;pa[14]=v3.z;pa[15]=v3.w;
            } else {
                int gr = row0 + tid;
                #pragma unroll
                for (int c = 0; c < 16; c++)
                    pa[c] = (gr < M && k0 + c < K) ? A[(size_t)gr*lda + k0 + c] : 0.f;
            }
            if (k0 + bk < K && col0 + 64 <= N) {
                const float* bp = B + (size_t)(k0 + bk)*ldb + col0 + bc;
                float4 v0=*(const float4*)bp, v1=*(const float4*)(bp+4);
                pb[0]=v0.x;pb[1]=v0.y;pb[2]=v0.z;pb[3]=v0.w;
                pb[4]=v1.x;pb[5]=v1.y;pb[6]=v1.z;pb[7]=v1.w;
            } else {
                #pragma unroll
                for (int c = 0; c < 8; c++) {
                    int gc = col0 + bc + c;
                    pb[c] = (k0 + bk < K && gc < N) ? B[(size_t)(k0+bk)*ldb + gc] : 0.f;
                }
            }
        }
        #pragma unroll
        for (int kk = 0; kk < 16; kk++) {
            const ulonglong2* ap2 = (const ulonglong2*)&As[cur][kk][ty*8];
            ulonglong2 aA = ap2[0];
            ulonglong2 aB = ap2[1];
            float4 bv0 = *(const float4*)&Bs[cur][kk][tx*8];
            float4 bv1 = *(const float4*)&Bs[cur][kk][tx*8+4];
            u64t b[8];
            b[0]=dup2(bv0.x); b[1]=dup2(bv0.y); b[2]=dup2(bv0.z); b[3]=dup2(bv0.w);
            b[4]=dup2(bv1.x); b[5]=dup2(bv1.y); b[6]=dup2(bv1.z); b[7]=dup2(bv1.w);
            #pragma unroll
            for (int j = 0; j < 8; j++) {
                ffma2(acc[0][j], aA.x, b[j]);
                ffma2(acc[1][j], aA.y, b[j]);
                ffma2(acc[2][j], aB.x, b[j]);
                ffma2(acc[3][j], aB.y, b[j]);
            }
        }
        if (kt + 1 < nkt) {
            int nxt = cur ^ 1;
            #pragma unroll
            for (int c = 0; c < 16; c++) As[nxt][c][tid] = pa[c];
            *(float4*)&Bs[nxt][bk][bc]   = make_float4(pb[0],pb[1],pb[2],pb[3]);
            *(float4*)&Bs[nxt][bk][bc+4] = make_float4(pb[4],pb[5],pb[6],pb[7]);
        }
        __syncthreads();
    }

    #pragma unroll
    for (int i = 0; i < 4; i++) {
        int r0 = row0 + ty*8 + i*2;
        #pragma unroll
        for (int j = 0; j < 8; j++) {
            int gc = col0 + tx*8 + j;
            if (gc >= N) continue;
            float2 p = unpack2(acc[i][j]);
            float bv = bias ? bias[gc] : 0.f;
            float v0 = p.x + bv, v1 = p.y + bv;
            if (act == 1) { v0 = tanhf(v0); v1 = tanhf(v1); }
            else if (act == 2) { v0 = (v0 > 0.f) ? v0 : 0.2f*v0; v1 = (v1 > 0.f) ? v1 : 0.2f*v1; }
            else if (act == 3) { v0 = fmaxf(v0, 0.f); v1 = fmaxf(v1, 0.f); }
            if (hm) {
                int f = gc / DD, d = gc - f*DD;
                size_t base = (size_t)f*NN*DD + d;
                if (r0     < M) C[base + (size_t)r0    *DD] = v0;
                if (r0 + 1 < M) C[base + (size_t)(r0+1)*DD] = v1;
            } else {
                if (r0     < M) C[(size_t)r0    *ldc + gc] = v0;
                if (r0 + 1 < M) C[(size_t)(r0+1)*ldc + gc] = v1;
            }
        }
    }
}

// ---------------- kw softmax over F axis (head-major) ------------------------
__global__ void k_kwsm(const float* __restrict__ raw, float* __restrict__ kw) {
    int i = blockIdx.x*blockDim.x + threadIdx.x;
    if (i >= NN*DD) return;
    const float* p = raw + i;
    const size_t S = (size_t)NN*DD;
    float a0 = __ldcs(p), a1 = __ldcs(p+S), a2 = __ldcs(p+2*S), a3 = __ldcs(p+3*S);
    float m = fmaxf(fmaxf(a0, a1), fmaxf(a2, a3));
    float e0 = __expf(a0-m), e1 = __expf(a1-m), e2 = __expf(a2-m), e3 = __expf(a3-m);
    float inv = 1.f/(e0+e1+e2+e3);
    float* q = kw + i;
    __stcs(q, e0*inv); __stcs(q+S, e1*inv); __stcs(q+2*S, e2*inv); __stcs(q+3*S, e3*inv);
}

// ---------------- attention layer: warp/node, 2 heads, streaming hints ------
// lane < 25 owns 8 consecutive d's. kw reads / xout writes are evict-first so
// the 64MB x gather working set stays L2-resident.
__global__ void k_layer2h(const float* __restrict__ x, const float* __restrict__ kw,
                          const float* __restrict__ r, float* __restrict__ xout,
                          int hb, int ilv) {
    int warp = threadIdx.x >> 5, lane = threadIdx.x & 31;
    int v = blockIdx.x*8 + warp;
    bool on = lane < 25;
    int off = lane * 8;
    const float* X0 = x + (size_t)hb    *NN*DD;
    const float* X1 = x + (size_t)(hb+1)*NN*DD;

    float xd0[8], xd1[8], acc0[8], acc1[8];
    #pragma unroll
    for (int j = 0; j < 8; j++) { xd0[j]=0.f; xd1[j]=0.f; acc0[j]=0.f; acc1[j]=0.f; }
    if (on) {
        const float4* p0 = (const float4*)(X0 + (size_t)v*DD + off);
        const float4* p1 = (const float4*)(X1 + (size_t)v*DD + off);
        float4 a = p0[0], b = p0[1];
        xd0[0]=a.x;xd0[1]=a.y;xd0[2]=a.z;xd0[3]=a.w; xd0[4]=b.x;xd0[5]=b.y;xd0[6]=b.z;xd0[7]=b.w;
        a = p1[0]; b = p1[1];
        xd1[0]=a.x;xd1[1]=a.y;xd1[2]=a.z;xd1[3]=a.w; xd1[4]=b.x;xd1[5]=b.y;xd1[6]=b.z;xd1[7]=b.w;
    }
    float rm0 = -INFINITY, rs0 = 0.f, rm1 = -INFINITY, rs1 = 0.f;

    int e0 = g_rowptr[v], e1 = g_rowptr[v+1];
    for (int eb = e0; eb < e1; eb += 2) {
        int m = min(2, e1 - eb);
        float xs0[2][8], xs1[2][8], rr[2][8];
        float p0v[2], p1v[2];
        #pragma unroll
        for (int c = 0; c < 2; c++) {
            p0v[c] = 0.f; p1v[c] = 0.f;
            if (c >= m) continue;
            int s  = g_csrc[eb+c];
            int et = g_cet[eb+c];
            if (on) {
                const float4* xp0 = (const float4*)(X0 + (size_t)s*DD + off);
                const float4* xp1 = (const float4*)(X1 + (size_t)s*DD + off);
                const float4* rp  = (const float4*)(r  + (size_t)et*DD + off);
                float4 a, b;
                a = xp0[0]; b = xp0[1];
                xs0[c][0]=a.x;xs0[c][1]=a.y;xs0[c][2]=a.z;xs0[c][3]=a.w;
                xs0[c][4]=b.x;xs0[c][5]=b.y;xs0[c][6]=b.z;xs0[c][7]=b.w;
                a = xp1[0]; b = xp1[1];
                xs1[c][0]=a.x;xs1[c][1]=a.y;xs1[c][2]=a.z;xs1[c][3]=a.w;
                xs1[c][4]=b.x;xs1[c][5]=b.y;xs1[c][6]=b.z;xs1[c][7]=b.w;
                a = rp[0]; b = rp[1];
                rr[c][0]=a.x;rr[c][1]=a.y;rr[c][2]=a.z;rr[c][3]=a.w;
                rr[c][4]=b.x;rr[c][5]=b.y;rr[c][6]=b.z;rr[c][7]=b.w;
                float s0 = 0.f, s1 = 0.f;
                #pragma unroll
                for (int j = 0; j < 8; j++) {
                    s0 += xs0[c][j]*rr[c][j]*xd0[j];
                    s1 += xs1[c][j]*rr[c][j]*xd1[j];
                }
                p0v[c] = s0; p1v[c] = s1;
            } else {
                #pragma unroll
                for (int j = 0; j < 8; j++) { xs0[c][j]=0.f; xs1[c][j]=0.f; rr[c][j]=0.f; }
            }
        }
        #pragma unroll
        for (int o = 16; o > 0; o >>= 1) {
            p0v[0] += __shfl_xor_sync(0xffffffffu, p0v[0], o);
            p0v[1] += __shfl_xor_sync(0xffffffffu, p0v[1], o);
            p1v[0] += __shfl_xor_sync(0xffffffffu, p1v[0], o);
            p1v[1] += __shfl_xor_sync(0xffffffffu, p1v[1], o);
        }
        #pragma unroll
        for (int c = 0; c < 2; c++) {
            if (c >= m) break;
            {
                float dot = p0v[c];
                float l = (dot > 0.f) ? dot : 0.2f*dot;
                float nm = fmaxf(rm0, l);
                float sc = (rm0 == -INFINITY) ? 0.f : __expf(rm0 - nm);
                float w = __expf(l - nm);
                rm0 = nm; rs0 = rs0*sc + w;
                #pragma unroll
                for (int j = 0; j < 8; j++)
                    acc0[j] = acc0[j]*sc + w*(xs0[c][j]*rr[c][j]);
            }
            {
                float dot = p1v[c];
                float l = (dot > 0.f) ? dot : 0.2f*dot;
                float nm = fmaxf(rm1, l);
                float sc = (rm1 == -INFINITY) ? 0.f : __expf(rm1 - nm);
                float w = __expf(l - nm);
                rm1 = nm; rs1 = rs1*sc + w;
                #pragma unroll
                for (int j = 0; j < 8; j++)
                    acc1[j] = acc1[j]*sc + w*(xs1[c][j]*rr[c][j]);
            }
        }
    }
    if (!on) return;
    float inv0 = 1.f/(rs0 + 1e-16f);
    float inv1 = 1.f/(rs1 + 1e-16f);
    const float4* kw0 = (const float4*)(kw + ((size_t)hb    *NN + v)*DD + off);
    const float4* kw1 = (const float4*)(kw + ((size_t)(hb+1)*NN + v)*DD + off);
    float4 k0a = __ldcs(kw0), k0b = __ldcs(kw0+1);
    float4 k1a = __ldcs(kw1), k1b = __ldcs(kw1+1);
    float kk0[8] = {k0a.x,k0a.y,k0a.z,k0a.w,k0b.x,k0b.y,k0b.z,k0b.w};
    float kk1[8] = {k1a.x,k1a.y,k1a.z,k1a.w,k1b.x,k1b.y,k1b.z,k1b.w};
    float o0[8], o1[8];
    #pragma unroll
    for (int j = 0; j < 8; j++) {
        o0[j] = tanhf(acc0[j]*inv0) * kk0[j];
        o1[j] = tanhf(acc1[j]*inv1) * kk1[j];
    }
    float* w0; float* w1;
    if (ilv) {
        w0 = xout + (size_t)v*FD + (size_t)hb    *DD + off;
        w1 = xout + (size_t)v*FD + (size_t)(hb+1)*DD + off;
    } else {
        w0 = xout + ((size_t)hb    *NN + v)*DD + off;
        w1 = xout + ((size_t)(hb+1)*NN + v)*DD + off;
    }
    __stcs((float4*)w0,     make_float4(o0[0],o0[1],o0[2],o0[3]));
    __stcs((float4*)w0 + 1, make_float4(o0[4],o0[5],o0[6],o0[7]));
    __stcs((float4*)w1,     make_float4(o1[0],o1[1],o1[2],o1[3]));
    __stcs((float4*)w1 + 1, make_float4(o1[4],o1[5],o1[6],o1[7]));
}

// ---------------- output gathers ----------------------------------------------
__global__ void k_subemb(const int* __restrict__ sub, const float* __restrict__ x,
                         float* __restrict__ o) {
    int b = blockIdx.x;
    int row = sub[b];
    for (int idx = threadIdx.x; idx < FD; idx += blockDim.x)
        o[(size_t)b*FD + idx] = x[(size_t)row*FD + idx];
}
__global__ void k_relemb(const int* __restrict__ rel, const float* __restrict__ ir,
                         float* __restrict__ o) {
    int b = blockIdx.x;
    int row = rel[b];
    for (int idx = threadIdx.x; idx < FD; idx += blockDim.x) {
        int d = idx % DD;
        o[(size_t)b*FD + idx] = ir[(size_t)row*DD + d];
    }
}

// ---------------- CLUB layer 1 (12 batched GEMMs, relu) ----------------------
__global__ void k_club1(const float* __restrict__ semb,
                        const float* __restrict__ mu_w1, const float* __restrict__ mu_b1,
                        const float* __restrict__ lv_w1, const float* __restrict__ lv_b1,
                        float* __restrict__ H) {
    const int ci[6] = {0,0,0,1,1,2};
    int z = blockIdx.z, cnt = z >> 1, net = z & 1;
    const float* A  = semb + ci[cnt]*DD;  // lda = FD
    const float* W  = (net ? lv_w1 : mu_w1) + (size_t)cnt*DD*HH2;
    const float* bb = (net ? lv_b1 : mu_b1) + cnt*HH2;
    float* C = H + (size_t)z*BB*HH2;

    __shared__ float As[8][64];
    __shared__ float Bs[8][65];
    int tid = threadIdx.x;
    int tx = tid & 15, ty = tid >> 4;
    int row0 = blockIdx.x*64, col0 = blockIdx.y*64;
    float acc[4][4] = {};
    for (int k0 = 0; k0 < DD; k0 += 8) {
        #pragma unroll
        for (int i = 0; i < 2; i++) {
            int idx = tid*2 + i;
            int rI = idx >> 3, kk = idx & 7;
            As[kk][rI] = A[(size_t)(row0+rI)*FD + k0 + kk];
        }
        #pragma unroll
        for (int i = 0; i < 2; i++) {
            int idx = tid + i*256;
            int kk = idx >> 6, c = idx & 63;
            int gc = col0 + c;
            Bs[kk][c] = (gc < HH2) ? W[(size_t)(k0+kk)*HH2 + gc] : 0.f;
        }
        __syncthreads();
        #pragma unroll
        for (int kk = 0; kk < 8; kk++) {
            float a[4], b[4];
            #pragma unroll
            for (int i = 0; i < 4; i++) a[i] = As[kk][ty*4+i];
            #pragma unroll
            for (int j = 0; j < 4; j++) b[j] = Bs[kk][tx*4+j];
            #pragma unroll
            for (int i = 0; i < 4; i++)
                #pragma unroll
                for (int j = 0; j < 4; j++)
                    acc[i][j] += a[i]*b[j];
        }
        __syncthreads();
    }
    #pragma unroll
    for (int i = 0; i < 4; i++) {
        int gr = row0 + ty*4 + i;
        #pragma unroll
        for (int j = 0; j < 4; j++) {
            int gc = col0 + tx*4 + j;
            if (gc < HH2)
                C[(size_t)gr*HH2 + gc] = fmaxf(acc[i][j] + bb[gc], 0.f);
        }
    }
}

// ---------------- CLUB layer 2 as batched GEMM (z = pair*2 + net) -----------
__global__ __launch_bounds__(128, 4)
void k_club2g(const float* __restrict__ mu_w2, const float* __restrict__ mu_b2,
              const float* __restrict__ lv_w2, const float* __restrict__ lv_b2) {
    __shared__ __align__(16) float As[2][16][128];
    __shared__ __align__(16) float Bs[2][16][64];
    int z = blockIdx.z, cnt = z >> 1, net = z & 1;
    const float* A  = g_h + (size_t)z*BB*HH2;
    const float* W  = (net ? lv_w2 : mu_w2) + (size_t)cnt*HH2*DD;
    const float* bb = (net ? lv_b2 : mu_b2) + cnt*DD;
    float* C = g_o2 + (size_t)z*BB*DD;
    const int N = DD, K = HH2;
    int tid = threadIdx.x;
    int tx = tid & 7, ty = tid >> 3;
    int row0 = blockIdx.x*128, col0 = blockIdx.y*64;
    int bk = tid >> 3, bc = (tid & 7) * 8;

    u64t acc[4][8];
    #pragma unroll
    for (int i = 0; i < 4; i++)
        #pragma unroll
        for (int j = 0; j < 8; j++) acc[i][j] = 0ull;

    float pa[16], pb[8];
    int nkt = (K + 15) >> 4;
    #pragma unroll 1
    for (int kt = -1; kt + 1 < nkt + 1; kt++) {
        if (kt + 1 < nkt) {
            int k0 = (kt + 1) * 16;
            int gr = row0 + tid;
            #pragma unroll
            for (int c = 0; c < 16; c++)
                pa[c] = (k0 + c < K) ? A[(size_t)gr*HH2 + k0 + c] : 0.f;
            #pragma unroll
            for (int c = 0; c < 8; c++) {
                int gc = col0 + bc + c;
                pb[c] = (k0 + bk < K && gc < N) ? W[(size_t)(k0+bk)*DD + gc] : 0.f;
            }
        }
        if (kt >= 0) {
            int cur = kt & 1;
            #pragma unroll
            for (int kk = 0; kk < 16; kk++) {
                const ulonglong2* ap2 = (const ulonglong2*)&As[cur][kk][ty*8];
                ulonglong2 aA = ap2[0];
                ulonglong2 aB = ap2[1];
                float4 bv0 = *(const float4*)&Bs[cur][kk][tx*8];
                float4 bv1 = *(const float4*)&Bs[cur][kk][tx*8+4];
                u64t b[8];
                b[0]=dup2(bv0.x); b[1]=dup2(bv0.y); b[2]=dup2(bv0.z); b[3]=dup2(bv0.w);
                b[4]=dup2(bv1.x); b[5]=dup2(bv1.y); b[6]=dup2(bv1.z); b[7]=dup2(bv1.w);
                #pragma unroll
                for (int j = 0; j < 8; j++) {
                    ffma2(acc[0][j], aA.x, b[j]);
                    ffma2(acc[1][j], aA.y, b[j]);
                    ffma2(acc[2][j], aB.x, b[j]);
                    ffma2(acc[3][j], aB.y, b[j]);
                }
            }
        }
        if (kt + 1 < nkt) {
            int nxt = (kt + 1) & 1;
            #pragma unroll
            for (int c = 0; c < 16; c++) As[nxt][c][tid] = pa[c];
            *(float4*)&Bs[nxt][bk][bc]   = make_float4(pb[0],pb[1],pb[2],pb[3]);
            *(float4*)&Bs[nxt][bk][bc+4] = make_float4(pb[4],pb[5],pb[6],pb[7]);
        }
        __syncthreads();
    }
    #pragma unroll
    for (int i = 0; i < 4; i++) {
        int r0 = row0 + ty*8 + i*2;
        #pragma unroll
        for (int j = 0; j < 8; j++) {
            int gc = col0 + tx*8 + j;
            if (gc >= N) continue;
            float2 p = unpack2(acc[i][j]);
            float bv = bb[gc];
            float v0 = p.x + bv, v1 = p.y + bv;
            if (net) { v0 = tanhf(v0); v1 = tanhf(v1); }
            C[(size_t)r0    *DD + gc] = v0;
            C[(size_t)(r0+1)*DD + gc] = v1;
        }
    }
}

// ---------------- loss reduction ----------------------------------------------
__global__ void k_loss(const float* __restrict__ semb, const int* __restrict__ perm,
                       float* __restrict__ mi) {
    const int cj[6] = {1,2,3,2,3,3};
    int b = blockIdx.x, cnt = blockIdx.y;
    __shared__ float red[256];
    int tid = threadIdx.x;
    float c = 0.f;
    if (tid < DD) {
        float mu = g_o2[((size_t)(cnt*2+0)*BB + b)*DD + tid];
        float lv = g_o2[((size_t)(cnt*2+1)*BB + b)*DD + tid];
        int j = cj[cnt];
        float yj  = semb[(size_t)b*FD + j*DD + tid];
        float yjp = semb[(size_t)perm[b]*FD + j*DD + tid];
        float d1 = mu - yj, d2 = mu - yjp;
        c = (d2*d2 - d1*d1) * expf(-lv);
    }
    red[tid] = c; __syncthreads();
    for (int o = 128; o > 0; o >>= 1) {
        if (tid < o) red[tid] += red[tid+o];
        __syncthreads();
    }
    if (tid == 0) atomicAdd(mi, red[0] * (0.5f/BB));
}

// ---------------- launch --------------------------------------------------------
extern "C" void kernel_launch(void* const* d_in, const int* in_sizes, int n_in,
                              void* d_out, int out_size) {
    const int*   sub        = (const int*)  d_in[0];
    const int*   rel        = (const int*)  d_in[1];
    const int*   eidx       = (const int*)  d_in[2];
    const int*   etype      = (const int*)  d_in[3];
    const int*   perm       = (const int*)  d_in[4];
    const float* init_embed = (const float*)d_in[5];
    const float* init_rel   = (const float*)d_in[6];
    const float* pca_w      = (const float*)d_in[7];
    const float* pca_b      = (const float*)d_in[8];
    const float* cw_w       = (const float*)d_in[9];
    const float* w_rel      = (const float*)d_in[10];
    const float* mu_w1      = (const float*)d_in[11];
    const float* mu_b1      = (const float*)d_in[12];
    const float* mu_w2      = (const float*)d_in[13];
    const float* mu_b2      = (const float*)d_in[14];
    const float* lv_w1      = (const float*)d_in[15];
    const float* lv_b1      = (const float*)d_in[16];
    const float* lv_w2      = (const float*)d_in[17];
    const float* lv_b2      = (const float*)d_in[18];
    float* out = (float*)d_out;

    const int* src = eidx;
    const int* dst = eidx + EE;

    float *xA, *xB, *kw, *r1, *H;
    cudaGetSymbolAddress((void**)&xA, g_xA);
    cudaGetSymbolAddress((void**)&xB, g_xB);
    cudaGetSymbolAddress((void**)&kw, g_kw);
    cudaGetSymbolAddress((void**)&r1, g_r1);
    cudaGetSymbolAddress((void**)&H, g_h);

    const int NB = (NN + 255)/256;

    // 1: zero
    k_zero<<<NB, 256>>>(out + MI_OFF);
    // 2: x0 GEMM (independent of CSR)
    {
        dim3 g((NN + 127)/128, (FD + 63)/64);
        k_sgemm4<<<g, 128>>>(init_embed, INITD, pca_w, FD, pca_b, xA, FD,
                             NN, FD, INITD, 1, 1);
    }
    // 3: hist
    k_hist<<<(EE + 255)/256, 256>>>(dst);
    // 4: kw GEMM  <-- ncu-captured launch
    {
        dim3 g((NN*FF + 127)/128, (DD + 63)/64);
        k_sgemm4<<<g, 128>>>(xA, DD, cw_w, DD, nullptr, xB, DD,
                             NN*FF, DD, DD, 2, 0);
    }
    // 5-7: CSR scans + fill
    k_scan1<<<NB, 256>>>();
    k_scan2<<<1, 256>>>(NB);
    k_scan3<<<NB, 256>>>();
    k_fill<<<(EE + 255)/256, 256>>>(src, dst, etype);

    // kw softmax
    k_kwsm<<<(NN*DD + 255)/256, 256>>>(xB, kw);

    // layer 0
    k_layer2h<<<NN/8, 256>>>(xA, kw, init_rel, xB, 0, 0);
    k_layer2h<<<NN/8, 256>>>(xA, kw, init_rel, xB, 2, 0);

    // r1 = init_rel @ w_rel[0]
    {
        dim3 g((NRELD + 127)/128, (DD + 63)/64);
        k_sgemm4<<<g, 128>>>(init_rel, DD, w_rel, DD, nullptr, r1, DD,
                             NRELD, DD, DD, 0, 0);
    }

    // layer 1 -> output x (interleaved)
    k_layer2h<<<NN/8, 256>>>(xB, kw, r1, out + X_OFF, 0, 1);
    k_layer2h<<<NN/8, 256>>>(xB, kw, r1, out + X_OFF, 2, 1);

    // gathers
    k_subemb<<<BB, 256>>>(sub, out + X_OFF, out + SUB_OFF);
    k_relemb<<<BB, 256>>>(rel, init_rel, out + REL_OFF);

    // CLUB
    {
        dim3 g(BB/64, (HH2 + 63)/64, 12);
        k_club1<<<g, 256>>>(out + SUB_OFF, mu_w1, mu_b1, lv_w1, lv_b1, H);
    }
    {
        dim3 g(BB/128, (DD + 63)/64, 12);
        k_club2g<<<g, 128>>>(mu_w2, mu_b2, lv_w2, lv_b2);
    }
    {
        dim3 g(BB, NPAIR);
        k_loss<<<g, 256>>>(out + SUB_OFF, perm, out + MI_OFF);
    }
}